// round 4
// baseline (speedup 1.0000x reference)
#include <cuda_runtime.h>
#include <cuda_bf16.h>
#include <cstdint>
#include <math.h>

// Problem constants
#define BB 4
#define TT 512
#define DD 512
#define HH 1024
#define VV 50000
#define VPAD 50048             // VV rounded up to 128
#define MROWS (BB*TT)          // 2048
#define G4H (4*HH)             // 4096
#define NB_REC 128             // recurrence grid blocks (all resident, 1 CTA/SM)
#define HC (HH/NB_REC)         // 8 h-cols per block

// ---------------- device scratch (static; zero-initialized) ------------------
__device__ __align__(256) __nv_bfloat16 g_emb [MROWS*DD];
__device__ __align__(256) __nv_bfloat16 g_Wih0[G4H*DD];
__device__ __align__(256) __nv_bfloat16 g_Wih1[G4H*HH];
__device__ __align__(256) __nv_bfloat16 g_Wout[(size_t)VPAD*HH];  // tail rows stay 0
__device__ __align__(256) float         g_xg  [MROWS*G4H];
__device__ __align__(256) __nv_bfloat16 g_h0  [MROWS*HH];
__device__ __align__(256) __nv_bfloat16 g_h1  [MROWS*HH];
__device__ __align__(256) float         g_hbuf[2*BB*HH];
__device__ __align__(256) int           g_flag[TT*NB_REC];   // per-CTA barrier flags
__device__ __align__(256) float         g_rowoff[MROWS];

// ---------------- small helpers ----------------------------------------------
__device__ __forceinline__ uint32_t smem_u32(const void* p) {
    return (uint32_t)__cvta_generic_to_shared(p);
}
__device__ __forceinline__ void ldmatrix_x4(uint32_t r[4], uint32_t addr) {
    asm volatile("ldmatrix.sync.aligned.m8n8.x4.shared.b16 {%0,%1,%2,%3}, [%4];"
                 : "=r"(r[0]), "=r"(r[1]), "=r"(r[2]), "=r"(r[3]) : "r"(addr));
}
__device__ __forceinline__ void ldmatrix_x2(uint32_t r[2], uint32_t addr) {
    asm volatile("ldmatrix.sync.aligned.m8n8.x2.shared.b16 {%0,%1}, [%2];"
                 : "=r"(r[0]), "=r"(r[1]) : "r"(addr));
}
__device__ __forceinline__ void mma16816(float d[4], const uint32_t a[4],
                                         const uint32_t b[2], const float c[4]) {
    asm volatile(
        "mma.sync.aligned.m16n8k16.row.col.f32.bf16.bf16.f32 "
        "{%0,%1,%2,%3}, {%4,%5,%6,%7}, {%8,%9}, {%10,%11,%12,%13};"
        : "=f"(d[0]), "=f"(d[1]), "=f"(d[2]), "=f"(d[3])
        : "r"(a[0]), "r"(a[1]), "r"(a[2]), "r"(a[3]),
          "r"(b[0]), "r"(b[1]),
          "f"(c[0]), "f"(c[1]), "f"(c[2]), "f"(c[3]));
}
__device__ __forceinline__ void ffma2(unsigned long long& d,
                                      unsigned long long a, unsigned long long b) {
    asm volatile("fma.rn.f32x2 %0, %1, %2, %0;" : "+l"(d) : "l"(a), "l"(b));
}
__device__ __forceinline__ float f32x2_sum(unsigned long long v) {
    float x, y;
    asm("mov.b64 {%0,%1}, %2;" : "=f"(x), "=f"(y) : "l"(v));
    return x + y;
}
__device__ __forceinline__ void cp_async16(uint32_t saddr, const void* g) {
    asm volatile("cp.async.cg.shared.global [%0], [%1], 16;" :: "r"(saddr), "l"(g));
}
__device__ __forceinline__ void cp_commit() {
    asm volatile("cp.async.commit_group;");
}
__device__ __forceinline__ int ld_acq(const int* p) {
    int v;
    asm volatile("ld.acquire.gpu.global.b32 %0, [%1];" : "=r"(v) : "l"(p) : "memory");
    return v;
}
__device__ __forceinline__ void st_rel(int* p, int v) {
    asm volatile("st.release.gpu.global.b32 [%0], %1;" :: "l"(p), "r"(v) : "memory");
}

// ---------------- conversion / gather kernels ---------------------------------
__global__ void f32_to_bf16_k(const float* __restrict__ in,
                              __nv_bfloat16* __restrict__ out, int n4) {
    int i = blockIdx.x * blockDim.x + threadIdx.x;
    if (i >= n4) return;
    float4 v = *((const float4*)in + i);
    __nv_bfloat162 lo = __floats2bfloat162_rn(v.x, v.y);
    __nv_bfloat162 hi = __floats2bfloat162_rn(v.z, v.w);
    uint2 u;
    u.x = *(uint32_t*)&lo; u.y = *(uint32_t*)&hi;
    *((uint2*)out + i) = u;
}

__global__ void gather_embed_k(const int* __restrict__ idx,
                               const float* __restrict__ X) {
    int i = blockIdx.x * blockDim.x + threadIdx.x;   // one float4 each
    if (i >= MROWS * (DD/4)) return;
    int r = i >> 7;             // DD/4 = 128
    int j = i & 127;
    int tok = __ldg(&idx[r]);
    float4 v = *(const float4*)(X + (size_t)tok * DD + j * 4);
    __nv_bfloat162 lo = __floats2bfloat162_rn(v.x, v.y);
    __nv_bfloat162 hi = __floats2bfloat162_rn(v.z, v.w);
    uint2 u; u.x = *(uint32_t*)&lo; u.y = *(uint32_t*)&hi;
    *((uint2*)(g_emb + (size_t)r * DD) + j) = u;
}

// ---------------- bf16 MMA GEMM: C[M,N] = A[M,K] * B[N,K]^T + bias ------------
// CTA tile 128x128, K-tile 64, cp.async 2-stage pipeline, 8 warps (2Mx4N).
#define GPITCH 72
#define GSTAGE (128*GPITCH)
#define GEMM_SMEM (4*GSTAGE*2)      // bytes

__global__ __launch_bounds__(256) void gemm_bf16_k(
    const __nv_bfloat16* __restrict__ A, const __nv_bfloat16* __restrict__ B,
    const float* __restrict__ bias, float* __restrict__ C,
    int M, int N, int K)
{
    extern __shared__ __nv_bfloat16 gsm[];
    __nv_bfloat16* sA = gsm;                 // [2][128][GPITCH]
    __nv_bfloat16* sB = gsm + 2*GSTAGE;      // [2][128][GPITCH]

    const int tid  = threadIdx.x;
    const int warp = tid >> 5, lane = tid & 31;
    const int wm = warp & 1, wn = warp >> 1;
    const int m0 = blockIdx.x * 128, n0 = blockIdx.y * 128;

    float acc[4][4][4];
#pragma unroll
    for (int a = 0; a < 4; a++)
#pragma unroll
        for (int b = 0; b < 4; b++)
#pragma unroll
            for (int c = 0; c < 4; c++) acc[a][b][c] = 0.f;

    const int ktiles = K >> 6;

    auto load_stage = [&](int st, int k0) {
#pragma unroll
        for (int i = 0; i < 4; i++) {
            int c   = tid + i * 256;
            int row = c >> 3;
            int col = (c & 7) << 3;
            uint32_t da = smem_u32(sA + st*GSTAGE + row*GPITCH + col);
            cp_async16(da, A + (size_t)(m0 + row) * K + k0 + col);
            uint32_t db = smem_u32(sB + st*GSTAGE + row*GPITCH + col);
            cp_async16(db, B + (size_t)(n0 + row) * K + k0 + col);
        }
    };

    load_stage(0, 0);
    cp_commit();

    for (int kt = 0; kt < ktiles; kt++) {
        if (kt + 1 < ktiles) {
            load_stage((kt + 1) & 1, (kt + 1) << 6);
            cp_commit();
            asm volatile("cp.async.wait_group 1;");
        } else {
            asm volatile("cp.async.wait_group 0;");
        }
        __syncthreads();

        const __nv_bfloat16* cA = sA + (kt & 1) * GSTAGE;
        const __nv_bfloat16* cB = sB + (kt & 1) * GSTAGE;
#pragma unroll
        for (int ks = 0; ks < 4; ks++) {
            uint32_t af[4][4], bf[4][2];
#pragma unroll
            for (int mt = 0; mt < 4; mt++) {
                uint32_t addr = smem_u32(
                    cA + (wm*64 + mt*16 + (lane & 15))*GPITCH
                       + ks*16 + ((lane >> 4) << 3));
                ldmatrix_x4(af[mt], addr);
            }
#pragma unroll
            for (int nt = 0; nt < 4; nt++) {
                uint32_t addr = smem_u32(
                    cB + (wn*32 + nt*8 + (lane & 7))*GPITCH
                       + ks*16 + (((lane >> 3) & 1) << 3));
                ldmatrix_x2(bf[nt], addr);
            }
#pragma unroll
            for (int mt = 0; mt < 4; mt++)
#pragma unroll
                for (int nt = 0; nt < 4; nt++)
                    mma16816(acc[mt][nt], af[mt], bf[nt], acc[mt][nt]);
        }
        __syncthreads();
    }

#pragma unroll
    for (int mt = 0; mt < 4; mt++)
#pragma unroll
        for (int nt = 0; nt < 4; nt++)
#pragma unroll
            for (int i = 0; i < 4; i++) {
                int row = m0 + wm*64 + mt*16 + (lane >> 2) + ((i >> 1) << 3);
                int col = n0 + wn*32 + nt*8 + ((lane & 3) << 1) + (i & 1);
                if (col < N)
                    C[(size_t)row * N + col] = acc[mt][nt][i] + __ldg(&bias[col]);
            }
}

// ---------------- persistent LSTM recurrence, W_hh in registers ---------------
// 128 CTAs, 256 threads. Thread (kh = tid>>5, lr = tid&31) holds
// W_hh[gate*HH + c0 + ci][kh*128 .. +128) in 128 registers (64 f32x2 pairs).
// Per step: poll per-CTA flags of t-1 (scalar ld.acquire), stage h (4096 f32)
// into smem, broadcast-read + FFMA2 dot, cross-warp reduce, activations,
// publish 32 h values + release-store flag. Slots self-reset with defer-by-2.
__global__ __launch_bounds__(256) void lstm_rec_k(
    const float* __restrict__ xg,
    const float* __restrict__ Whh,
    __nv_bfloat16* __restrict__ hseq)
{
    __shared__ __align__(16) float hsm [4*HH];      // h_{t-1}, [b][k]
    __shared__ __align__(16) float part[8*32*4];    // [kh][lr][b]
    __shared__ float gsm[128];
    __shared__ float csm[32];

    const int tid  = threadIdx.x;
    const int bk   = blockIdx.x;
    const int c0   = bk * HC;
    const int kh   = tid >> 5;      // k-eighth (== warp id)
    const int lr   = tid & 31;      // local gate-row
    const int gate = lr >> 3, ci = lr & 7;
    const int lane = tid & 31;

    // clear stale flag slots from the previous launch (own byte only)
    if (tid == 0) {
        g_flag[(TT-2)*NB_REC + bk] = 0;
        g_flag[(TT-1)*NB_REC + bk] = 0;
    }

    // ---- load this thread's 128 W_hh weights into registers ----
    unsigned long long W[64];
    {
        const float* wsrc = Whh + (size_t)(gate*HH + c0 + ci) * HH + kh * 128;
        union { float4 f; ulonglong2 u; } cv;
#pragma unroll
        for (int i = 0; i < 32; i++) {
            cv.f = __ldg((const float4*)(wsrc + 4*i));
            W[2*i]   = cv.u.x;
            W[2*i+1] = cv.u.y;
        }
    }
    if (tid < 32) csm[tid] = 0.f;

    // reduction-thread mapping (tid < 128): tid = lr2*4 + b2
    const int lr2 = tid >> 2, b2 = tid & 3;
    const int gate2 = lr2 >> 3, ci2 = lr2 & 7;
    const float* xgp = xg + (size_t)b2*TT*G4H + gate2*HH + c0 + ci2;

    __syncthreads();

    for (int t = 0; t < TT; t++) {
        // prefetch xg early (independent of barrier)
        float xgv = 0.f;
        if (tid < 128) xgv = __ldg(xgp + (size_t)t * G4H);

        unsigned long long accA[4] = {0ull,0ull,0ull,0ull};
        unsigned long long accB[4] = {0ull,0ull,0ull,0ull};

        if (t > 0) {
            // ---- wait for all CTAs' h_{t-1} (per-CTA flags, acquire loads) ----
            const int* fl = g_flag + (t-1)*NB_REC;
            for (;;) {
                int a = ld_acq(fl + lane);
                int b = ld_acq(fl + lane + 32);
                int c = ld_acq(fl + lane + 64);
                int d = ld_acq(fl + lane + 96);
                int ok = a & b & c & d;
                if (__ballot_sync(0xffffffffu, ok) == 0xffffffffu) break;
            }
            // defer-by-2 self-reset: everyone passed t-2's poll by now
            if (t >= 2 && tid == 0) g_flag[(t-2)*NB_REC + bk] = 0;

            // ---- stage h_{t-1} into smem ----
            const float* hsrc = g_hbuf + (t & 1) * BB * HH;
#pragma unroll
            for (int i = 0; i < 4; i++) {
                int f = tid + i * 256;
                float4 v = __ldcg((const float4*)(hsrc + 4*f));
                *(float4*)&hsm[4*f] = v;
            }
            __syncthreads();

            // ---- dot: this thread's 128 weights x 4 batches (broadcast h) ----
            const float* hb = hsm + kh * 128;
#pragma unroll
            for (int j = 0; j < 32; j++) {
#pragma unroll
                for (int b = 0; b < 4; b++) {
                    ulonglong2 hp = *(const ulonglong2*)(hb + b*HH + 4*j);
                    ffma2(accA[b], W[2*j],   hp.x);
                    ffma2(accB[b], W[2*j+1], hp.y);
                }
            }
        }

        // store partials: part[kh][lr][b]
        float4 ps;
        ps.x = f32x2_sum(accA[0]) + f32x2_sum(accB[0]);
        ps.y = f32x2_sum(accA[1]) + f32x2_sum(accB[1]);
        ps.z = f32x2_sum(accA[2]) + f32x2_sum(accB[2]);
        ps.w = f32x2_sum(accA[3]) + f32x2_sum(accB[3]);
        *(float4*)&part[tid*4] = ps;
        __syncthreads();

        // cross-warp reduce + xg
        if (tid < 128) {
            float g = xgv;
#pragma unroll
            for (int k8 = 0; k8 < 8; k8++) g += part[k8*128 + tid];
            gsm[tid] = g;
        }
        __syncthreads();

        // activations + publish h (32 cells x 4 batches -> this CTA owns 8 cells)
        if (tid < 32) {
            int cc = tid >> 2, b = tid & 3;
            float iv = gsm[((0*8 + cc) << 2) + b];
            float fv = gsm[((1*8 + cc) << 2) + b];
            float gv = gsm[((2*8 + cc) << 2) + b];
            float ov = gsm[((3*8 + cc) << 2) + b];
            iv = 1.f / (1.f + __expf(-iv));
            fv = 1.f / (1.f + __expf(-fv));
            gv = tanhf(gv);
            ov = 1.f / (1.f + __expf(-ov));
            float c = fv * csm[tid] + iv * gv;
            csm[tid] = c;
            float h = ov * tanhf(c);
            g_hbuf[((t + 1) & 1) * BB * HH + b * HH + c0 + cc] = h;
            hseq[(size_t)(b*TT + t) * HH + c0 + cc] = __float2bfloat16(h);
        }
        __syncthreads();   // h writes done CTA-wide before the release store

        if (tid == 0) st_rel(&g_flag[t*NB_REC + bk], 1);
    }
}

// ---------------- log-softmax (logits tiny -> no max subtraction) -------------
__global__ void rowsum_k(const float* __restrict__ C) {
    __shared__ float red[256];
    const int row = blockIdx.x;
    const int tid = threadIdx.x;
    const float4* p = (const float4*)(C + (size_t)row * VV);
    const int n4 = VV / 4;   // 12500

    float sum = 0.f;
    for (int i = tid; i < n4; i += 256) {
        float4 v = p[i];
        sum += __expf(v.x) + __expf(v.y) + __expf(v.z) + __expf(v.w);
    }
    red[tid] = sum; __syncthreads();
    for (int s = 128; s > 0; s >>= 1) {
        if (tid < s) red[tid] += red[tid + s];
        __syncthreads();
    }
    if (tid == 0) g_rowoff[row] = logf(red[0]);
}

__global__ void logsm_apply_k(float* __restrict__ C) {
    const int row = blockIdx.y;
    const int i = blockIdx.x * blockDim.x + threadIdx.x;
    if (i >= VV/4) return;
    float4* p = (float4*)(C + (size_t)row * VV);
    float off = __ldg(&g_rowoff[row]);
    float4 v = p[i];
    v.x -= off; v.y -= off; v.z -= off; v.w -= off;
    p[i] = v;
}

// ---------------- launcher ----------------------------------------------------
extern "C" void kernel_launch(void* const* d_in, const int* in_sizes, int n_in,
                              void* d_out, int out_size) {
    const int*   token_idx = (const int*)  d_in[0];
    const float* X     = (const float*)d_in[1];
    const float* W_ih0 = (const float*)d_in[2];
    const float* W_hh0 = (const float*)d_in[3];
    const float* b0    = (const float*)d_in[4];
    const float* W_ih1 = (const float*)d_in[5];
    const float* W_hh1 = (const float*)d_in[6];
    const float* b1    = (const float*)d_in[7];
    const float* W_out = (const float*)d_in[8];
    const float* b_out = (const float*)d_in[9];
    float* out = (float*)d_out;

    cudaFuncSetAttribute(gemm_bf16_k,
                         cudaFuncAttributeMaxDynamicSharedMemorySize,
                         GEMM_SMEM);

    void *p_emb, *p_Wih0, *p_Wih1, *p_Wout, *p_xg, *p_h0, *p_h1;
    cudaGetSymbolAddress(&p_emb,  g_emb);
    cudaGetSymbolAddress(&p_Wih0, g_Wih0);
    cudaGetSymbolAddress(&p_Wih1, g_Wih1);
    cudaGetSymbolAddress(&p_Wout, g_Wout);
    cudaGetSymbolAddress(&p_xg,   g_xg);
    cudaGetSymbolAddress(&p_h0,   g_h0);
    cudaGetSymbolAddress(&p_h1,   g_h1);

    // layer 0
    gather_embed_k<<<(MROWS*(DD/4) + 255)/256, 256>>>(token_idx, X);
    f32_to_bf16_k<<<(G4H*DD/4 + 255)/256, 256>>>(W_ih0, (__nv_bfloat16*)p_Wih0, G4H*DD/4);
    gemm_bf16_k<<<dim3(MROWS/128, G4H/128), 256, GEMM_SMEM>>>(
        (const __nv_bfloat16*)p_emb, (const __nv_bfloat16*)p_Wih0, b0,
        (float*)p_xg, MROWS, G4H, DD);
    lstm_rec_k<<<NB_REC, 256>>>(
        (const float*)p_xg, W_hh0, (__nv_bfloat16*)p_h0);

    // layer 1
    f32_to_bf16_k<<<(G4H*HH/4 + 255)/256, 256>>>(W_ih1, (__nv_bfloat16*)p_Wih1, G4H*HH/4);
    gemm_bf16_k<<<dim3(MROWS/128, G4H/128), 256, GEMM_SMEM>>>(
        (const __nv_bfloat16*)p_h0, (const __nv_bfloat16*)p_Wih1, b1,
        (float*)p_xg, MROWS, G4H, HH);
    lstm_rec_k<<<NB_REC, 256>>>(
        (const float*)p_xg, W_hh1, (__nv_bfloat16*)p_h1);

    // output projection + log-softmax
    f32_to_bf16_k<<<(VV*HH/4 + 255)/256, 256>>>(W_out, (__nv_bfloat16*)p_Wout, VV*HH/4);
    gemm_bf16_k<<<dim3(MROWS/128, VPAD/128), 256, GEMM_SMEM>>>(
        (const __nv_bfloat16*)p_h1, (const __nv_bfloat16*)p_Wout, b_out,
        out, MROWS, VV, HH);
    rowsum_k<<<MROWS, 256>>>(out);
    logsm_apply_k<<<dim3((VV/4 + 255)/256, MROWS), 256>>>(out);
}

// round 5
// speedup vs baseline: 1.9101x; 1.9101x over previous
#include <cuda_runtime.h>
#include <cuda_bf16.h>
#include <cstdint>
#include <math.h>

// Problem constants
#define BB 4
#define TT 512
#define DD 512
#define HH 1024
#define VV 50000
#define VPAD 50048             // VV rounded up to 128
#define MROWS (BB*TT)          // 2048
#define G4H (4*HH)             // 4096
#define NB_REC 128             // recurrence CTAs (<=148, all resident wave-1)
#define NCHUNK 16              // h broadcast chunks per step (8 CTAs / 64 cols each)
#define CPC 8                  // CTAs per chunk

// ---------------- device scratch (static; zero-initialized) ------------------
__device__ __align__(256) __nv_bfloat16 g_emb [MROWS*DD];
__device__ __align__(256) __nv_bfloat16 g_Wih0[G4H*DD];
__device__ __align__(256) __nv_bfloat16 g_Wih1[G4H*HH];
__device__ __align__(256) __nv_bfloat16 g_Wout[(size_t)VPAD*HH];  // tail rows stay 0
__device__ __align__(256) float         g_xg  [MROWS*G4H];
__device__ __align__(256) __nv_bfloat16 g_h0  [MROWS*HH];
__device__ __align__(256) __nv_bfloat16 g_h1  [MROWS*HH];
__device__ __align__(256) float         g_hbuf[2*BB*HH];
__device__ __align__(256) int           g_cnt [TT][NCHUNK][32];  // counter @[..][0], 128B apart
__device__ __align__(256) float         g_rowoff[MROWS];

// ---------------- small helpers ----------------------------------------------
__device__ __forceinline__ uint32_t smem_u32(const void* p) {
    return (uint32_t)__cvta_generic_to_shared(p);
}
__device__ __forceinline__ void ldmatrix_x4(uint32_t r[4], uint32_t addr) {
    asm volatile("ldmatrix.sync.aligned.m8n8.x4.shared.b16 {%0,%1,%2,%3}, [%4];"
                 : "=r"(r[0]), "=r"(r[1]), "=r"(r[2]), "=r"(r[3]) : "r"(addr));
}
__device__ __forceinline__ void ldmatrix_x2(uint32_t r[2], uint32_t addr) {
    asm volatile("ldmatrix.sync.aligned.m8n8.x2.shared.b16 {%0,%1}, [%2];"
                 : "=r"(r[0]), "=r"(r[1]) : "r"(addr));
}
__device__ __forceinline__ void mma16816(float d[4], const uint32_t a[4],
                                         const uint32_t b[2], const float c[4]) {
    asm volatile(
        "mma.sync.aligned.m16n8k16.row.col.f32.bf16.bf16.f32 "
        "{%0,%1,%2,%3}, {%4,%5,%6,%7}, {%8,%9}, {%10,%11,%12,%13};"
        : "=f"(d[0]), "=f"(d[1]), "=f"(d[2]), "=f"(d[3])
        : "r"(a[0]), "r"(a[1]), "r"(a[2]), "r"(a[3]),
          "r"(b[0]), "r"(b[1]),
          "f"(c[0]), "f"(c[1]), "f"(c[2]), "f"(c[3]));
}
__device__ __forceinline__ void ffma2(unsigned long long& d,
                                      unsigned long long a, unsigned long long b) {
    asm volatile("fma.rn.f32x2 %0, %1, %2, %0;" : "+l"(d) : "l"(a), "l"(b));
}
__device__ __forceinline__ float f32x2_sum(unsigned long long v) {
    float x, y;
    asm("mov.b64 {%0,%1}, %2;" : "=f"(x), "=f"(y) : "l"(v));
    return x + y;
}
__device__ __forceinline__ void cp_async16(uint32_t saddr, const void* g) {
    asm volatile("cp.async.cg.shared.global [%0], [%1], 16;" :: "r"(saddr), "l"(g));
}
__device__ __forceinline__ void cp_commit() {
    asm volatile("cp.async.commit_group;");
}
__device__ __forceinline__ int ld_acq(const int* p) {
    int v;
    asm volatile("ld.acquire.gpu.global.b32 %0, [%1];" : "=r"(v) : "l"(p) : "memory");
    return v;
}

// ---------------- conversion / gather kernels ---------------------------------
__global__ void f32_to_bf16_k(const float* __restrict__ in,
                              __nv_bfloat16* __restrict__ out, int n4) {
    int i = blockIdx.x * blockDim.x + threadIdx.x;
    if (i >= n4) return;
    float4 v = *((const float4*)in + i);
    __nv_bfloat162 lo = __floats2bfloat162_rn(v.x, v.y);
    __nv_bfloat162 hi = __floats2bfloat162_rn(v.z, v.w);
    uint2 u;
    u.x = *(uint32_t*)&lo; u.y = *(uint32_t*)&hi;
    *((uint2*)out + i) = u;
}

__global__ void gather_embed_k(const int* __restrict__ idx,
                               const float* __restrict__ X) {
    int i = blockIdx.x * blockDim.x + threadIdx.x;   // one float4 each
    if (i >= MROWS * (DD/4)) return;
    int r = i >> 7;             // DD/4 = 128
    int j = i & 127;
    int tok = __ldg(&idx[r]);
    float4 v = *(const float4*)(X + (size_t)tok * DD + j * 4);
    __nv_bfloat162 lo = __floats2bfloat162_rn(v.x, v.y);
    __nv_bfloat162 hi = __floats2bfloat162_rn(v.z, v.w);
    uint2 u; u.x = *(uint32_t*)&lo; u.y = *(uint32_t*)&hi;
    *((uint2*)(g_emb + (size_t)r * DD) + j) = u;
}

// ---------------- bf16 MMA GEMM: C[M,N] = A[M,K] * B[N,K]^T + bias ------------
// CTA tile 128x128, K-tile 64, cp.async 2-stage pipeline, 8 warps (2Mx4N).
#define GPITCH 72
#define GSTAGE (128*GPITCH)
#define GEMM_SMEM (4*GSTAGE*2)      // bytes

__global__ __launch_bounds__(256) void gemm_bf16_k(
    const __nv_bfloat16* __restrict__ A, const __nv_bfloat16* __restrict__ B,
    const float* __restrict__ bias, float* __restrict__ C,
    int M, int N, int K)
{
    extern __shared__ __nv_bfloat16 gsm_[];
    __nv_bfloat16* sA = gsm_;                // [2][128][GPITCH]
    __nv_bfloat16* sB = gsm_ + 2*GSTAGE;     // [2][128][GPITCH]

    const int tid  = threadIdx.x;
    const int warp = tid >> 5, lane = tid & 31;
    const int wm = warp & 1, wn = warp >> 1;
    const int m0 = blockIdx.x * 128, n0 = blockIdx.y * 128;

    float acc[4][4][4];
#pragma unroll
    for (int a = 0; a < 4; a++)
#pragma unroll
        for (int b = 0; b < 4; b++)
#pragma unroll
            for (int c = 0; c < 4; c++) acc[a][b][c] = 0.f;

    const int ktiles = K >> 6;

    auto load_stage = [&](int st, int k0) {
#pragma unroll
        for (int i = 0; i < 4; i++) {
            int c   = tid + i * 256;
            int row = c >> 3;
            int col = (c & 7) << 3;
            uint32_t da = smem_u32(sA + st*GSTAGE + row*GPITCH + col);
            cp_async16(da, A + (size_t)(m0 + row) * K + k0 + col);
            uint32_t db = smem_u32(sB + st*GSTAGE + row*GPITCH + col);
            cp_async16(db, B + (size_t)(n0 + row) * K + k0 + col);
        }
    };

    load_stage(0, 0);
    cp_commit();

    for (int kt = 0; kt < ktiles; kt++) {
        if (kt + 1 < ktiles) {
            load_stage((kt + 1) & 1, (kt + 1) << 6);
            cp_commit();
            asm volatile("cp.async.wait_group 1;");
        } else {
            asm volatile("cp.async.wait_group 0;");
        }
        __syncthreads();

        const __nv_bfloat16* cA = sA + (kt & 1) * GSTAGE;
        const __nv_bfloat16* cB = sB + (kt & 1) * GSTAGE;
#pragma unroll
        for (int ks = 0; ks < 4; ks++) {
            uint32_t af[4][4], bf[4][2];
#pragma unroll
            for (int mt = 0; mt < 4; mt++) {
                uint32_t addr = smem_u32(
                    cA + (wm*64 + mt*16 + (lane & 15))*GPITCH
                       + ks*16 + ((lane >> 4) << 3));
                ldmatrix_x4(af[mt], addr);
            }
#pragma unroll
            for (int nt = 0; nt < 4; nt++) {
                uint32_t addr = smem_u32(
                    cB + (wn*32 + nt*8 + (lane & 7))*GPITCH
                       + ks*16 + (((lane >> 3) & 1) << 3));
                ldmatrix_x2(bf[nt], addr);
            }
#pragma unroll
            for (int mt = 0; mt < 4; mt++)
#pragma unroll
                for (int nt = 0; nt < 4; nt++)
                    mma16816(acc[mt][nt], af[mt], bf[nt], acc[mt][nt]);
        }
        __syncthreads();
    }

#pragma unroll
    for (int mt = 0; mt < 4; mt++)
#pragma unroll
        for (int nt = 0; nt < 4; nt++)
#pragma unroll
            for (int i = 0; i < 4; i++) {
                int row = m0 + wm*64 + mt*16 + (lane >> 2) + ((i >> 1) << 3);
                int col = n0 + wn*32 + nt*8 + ((lane & 3) << 1) + (i & 1);
                if (col < N)
                    C[(size_t)row * N + col] = acc[mt][nt][i] + __ldg(&bias[col]);
            }
}

// ---------------- persistent LSTM recurrence, chunked h exchange --------------
// 128 CTAs x 256 threads. Thread (warp ke = tid>>5, row r = tid&31) holds
// W_hh[gate*HH + c0 + ci][128*ke .. +128) in 128 registers.
// h_{t-1} is consumed in 16 chunks of 64 columns; warp ke needs only chunks
// {2ke, 2ke+1}. Each chunk has its own counter (g_cnt[t][ch][0], own line);
// producers fence+red.release after publishing their 8 h-cells; consumers
// acquire-poll just their own chunk counters -> skew and barrier latency are
// overlapped with the dot instead of serialized. Slots recycle defer-by-2.
__global__ __launch_bounds__(256) void lstm_rec_k(
    const float* __restrict__ xg,
    const float* __restrict__ Whh,
    __nv_bfloat16* __restrict__ hseq)
{
    __shared__ __align__(16) float hstage[8][2][4][64];  // [warp][half][b][k] 16KB
    __shared__ __align__(16) float part[256*4];          // [tid][b]
    __shared__ float gsm[128];
    __shared__ float csm[32];

    const int tid  = threadIdx.x;
    const int bk   = blockIdx.x;
    const int c0   = bk * 8;
    const int ke   = tid >> 5;      // warp = k-eighth
    const int r    = tid & 31;      // local gate-row
    const int lane = tid & 31;
    const int gate = r >> 3, ci = r & 7;

    // clear the two counter slots the previous launch left set
    if (bk < NCHUNK && tid == 0) {
        g_cnt[TT-2][bk][0] = 0;
        g_cnt[TT-1][bk][0] = 0;
    }

    // ---- this thread's 128 W_hh weights -> registers (as 64 f32x2) ----
    unsigned long long W[64];
    {
        const float* wsrc = Whh + (size_t)(gate*HH + c0 + ci) * HH + ke * 128;
        union { float4 f; ulonglong2 u; } cv;
#pragma unroll
        for (int i = 0; i < 32; i++) {
            cv.f = __ldg((const float4*)(wsrc + 4*i));
            W[2*i]   = cv.u.x;
            W[2*i+1] = cv.u.y;
        }
    }
    if (tid < 32) csm[tid] = 0.f;

    // reducer mapping (tid < 128): r2 = gate-row, b2 = batch
    const int r2 = tid >> 2, b2 = tid & 3;
    const float* xgp = xg + (size_t)b2*TT*G4H + (r2 >> 3)*HH + c0 + (r2 & 7);

    __syncthreads();

    for (int t = 0; t < TT; t++) {
        // prefetch the additive xg term (independent of h)
        float xgv = 0.f;
        if (tid < 128) xgv = __ldg(xgp + (size_t)t * G4H);

        unsigned long long accA[4] = {0ull,0ull,0ull,0ull};
        unsigned long long accB[4] = {0ull,0ull,0ull,0ull};

        if (t > 0) {
            const float* hsrc = g_hbuf + (t & 1) * BB * HH;
#pragma unroll
            for (int half = 0; half < 2; half++) {
                const int ch = 2*ke + half;
                // acquire-poll this chunk's counter (all lanes, one L2 line)
                const int* cp = &g_cnt[t-1][ch][0];
                int v;
                do { v = ld_acq(cp); } while (v < CPC);

                // stage the 1KB chunk coalesced (2 float4 per lane)
#pragma unroll
                for (int q = 0; q < 2; q++) {
                    int ii = lane + q*32;          // 0..63
                    int b = ii >> 4, j = ii & 15;
                    float4 hv = __ldcg((const float4*)(hsrc + b*HH + ch*64 + 4*j));
                    *(float4*)&hstage[ke][half][b][4*j] = hv;
                }
                __syncwarp();

                // dot over this 64-col chunk, 4 batches (broadcast LDS)
#pragma unroll
                for (int j = 0; j < 16; j++) {
#pragma unroll
                    for (int b = 0; b < 4; b++) {
                        union { float4 f; ulonglong2 u; } hv;
                        hv.f = *(const float4*)&hstage[ke][half][b][4*j];
                        ffma2(accA[b], W[32*half + 2*j],     hv.u.x);
                        ffma2(accB[b], W[32*half + 2*j + 1], hv.u.y);
                    }
                }
            }
            // recycle slot t-2: all CTAs are provably past their t-2 polls
            if (t >= 2 && bk < NCHUNK && tid == 32) g_cnt[t-2][bk][0] = 0;
        }

        float4 ps;
        ps.x = f32x2_sum(accA[0]) + f32x2_sum(accB[0]);
        ps.y = f32x2_sum(accA[1]) + f32x2_sum(accB[1]);
        ps.z = f32x2_sum(accA[2]) + f32x2_sum(accB[2]);
        ps.w = f32x2_sum(accA[3]) + f32x2_sum(accB[3]);
        *(float4*)&part[tid*4] = ps;
        __syncthreads();

        // reduce 8 k-eighths + xg
        if (tid < 128) {
            float g = xgv;
#pragma unroll
            for (int k8 = 0; k8 < 8; k8++) g += part[k8*128 + tid];
            gsm[tid] = g;
        }
        __syncthreads();

        // activations + publish 8 cells x 4 batches (warp 0 only)
        if (tid < 32) {
            int cc = tid >> 2, b = tid & 3;
            float iv = gsm[((0*8 + cc) << 2) + b];
            float fv = gsm[((1*8 + cc) << 2) + b];
            float gv = gsm[((2*8 + cc) << 2) + b];
            float ov = gsm[((3*8 + cc) << 2) + b];
            iv = 1.f / (1.f + __expf(-iv));
            fv = 1.f / (1.f + __expf(-fv));
            gv = tanhf(gv);
            ov = 1.f / (1.f + __expf(-ov));
            float c = fv * csm[tid] + iv * gv;
            csm[tid] = c;
            float h = ov * tanhf(c);
            g_hbuf[((t + 1) & 1) * BB * HH + b * HH + c0 + cc] = h;
            hseq[(size_t)(b*TT + t) * HH + c0 + cc] = __float2bfloat16(h);
        }
        __syncwarp();      // warp0: h stores complete before the release below
        if (tid == 0) {
            asm volatile("fence.acq_rel.gpu;" ::: "memory");
            int one = 1;
            asm volatile("red.release.gpu.global.add.s32 [%0], %1;"
                         :: "l"(&g_cnt[t][bk >> 3][0]), "r"(one) : "memory");
        }
        // next iteration's first __syncthreads realigns the CTA; smem reuse is
        // protected by the counter chain (no thread can write part/gsm for t+1
        // before passing sync that warp0 also reaches).
    }
}

// ---------------- log-softmax (logits tiny -> no max subtraction) -------------
__global__ void rowsum_k(const float* __restrict__ C) {
    __shared__ float red[256];
    const int row = blockIdx.x;
    const int tid = threadIdx.x;
    const float4* p = (const float4*)(C + (size_t)row * VV);
    const int n4 = VV / 4;   // 12500

    float sum = 0.f;
    for (int i = tid; i < n4; i += 256) {
        float4 v = p[i];
        sum += __expf(v.x) + __expf(v.y) + __expf(v.z) + __expf(v.w);
    }
    red[tid] = sum; __syncthreads();
    for (int s = 128; s > 0; s >>= 1) {
        if (tid < s) red[tid] += red[tid + s];
        __syncthreads();
    }
    if (tid == 0) g_rowoff[row] = logf(red[0]);
}

__global__ void logsm_apply_k(float* __restrict__ C) {
    const int row = blockIdx.y;
    const int i = blockIdx.x * blockDim.x + threadIdx.x;
    if (i >= VV/4) return;
    float4* p = (float4*)(C + (size_t)row * VV);
    float off = __ldg(&g_rowoff[row]);
    float4 v = p[i];
    v.x -= off; v.y -= off; v.z -= off; v.w -= off;
    p[i] = v;
}

// ---------------- launcher ----------------------------------------------------
extern "C" void kernel_launch(void* const* d_in, const int* in_sizes, int n_in,
                              void* d_out, int out_size) {
    const int*   token_idx = (const int*)  d_in[0];
    const float* X     = (const float*)d_in[1];
    const float* W_ih0 = (const float*)d_in[2];
    const float* W_hh0 = (const float*)d_in[3];
    const float* b0    = (const float*)d_in[4];
    const float* W_ih1 = (const float*)d_in[5];
    const float* W_hh1 = (const float*)d_in[6];
    const float* b1    = (const float*)d_in[7];
    const float* W_out = (const float*)d_in[8];
    const float* b_out = (const float*)d_in[9];
    float* out = (float*)d_out;

    cudaFuncSetAttribute(gemm_bf16_k,
                         cudaFuncAttributeMaxDynamicSharedMemorySize,
                         GEMM_SMEM);

    void *p_emb, *p_Wih0, *p_Wih1, *p_Wout, *p_xg, *p_h0, *p_h1;
    cudaGetSymbolAddress(&p_emb,  g_emb);
    cudaGetSymbolAddress(&p_Wih0, g_Wih0);
    cudaGetSymbolAddress(&p_Wih1, g_Wih1);
    cudaGetSymbolAddress(&p_Wout, g_Wout);
    cudaGetSymbolAddress(&p_xg,   g_xg);
    cudaGetSymbolAddress(&p_h0,   g_h0);
    cudaGetSymbolAddress(&p_h1,   g_h1);

    // layer 0
    gather_embed_k<<<(MROWS*(DD/4) + 255)/256, 256>>>(token_idx, X);
    f32_to_bf16_k<<<(G4H*DD/4 + 255)/256, 256>>>(W_ih0, (__nv_bfloat16*)p_Wih0, G4H*DD/4);
    gemm_bf16_k<<<dim3(MROWS/128, G4H/128), 256, GEMM_SMEM>>>(
        (const __nv_bfloat16*)p_emb, (const __nv_bfloat16*)p_Wih0, b0,
        (float*)p_xg, MROWS, G4H, DD);
    lstm_rec_k<<<NB_REC, 256>>>(
        (const float*)p_xg, W_hh0, (__nv_bfloat16*)p_h0);

    // layer 1
    f32_to_bf16_k<<<(G4H*HH/4 + 255)/256, 256>>>(W_ih1, (__nv_bfloat16*)p_Wih1, G4H*HH/4);
    gemm_bf16_k<<<dim3(MROWS/128, G4H/128), 256, GEMM_SMEM>>>(
        (const __nv_bfloat16*)p_h0, (const __nv_bfloat16*)p_Wih1, b1,
        (float*)p_xg, MROWS, G4H, HH);
    lstm_rec_k<<<NB_REC, 256>>>(
        (const float*)p_xg, W_hh1, (__nv_bfloat16*)p_h1);

    // output projection + log-softmax
    f32_to_bf16_k<<<(VV*HH/4 + 255)/256, 256>>>(W_out, (__nv_bfloat16*)p_Wout, VV*HH/4);
    gemm_bf16_k<<<dim3(MROWS/128, VPAD/128), 256, GEMM_SMEM>>>(
        (const __nv_bfloat16*)p_h1, (const __nv_bfloat16*)p_Wout, b_out,
        out, MROWS, VV, HH);
    rowsum_k<<<MROWS, 256>>>(out);
    logsm_apply_k<<<dim3((VV/4 + 255)/256, MROWS), 256>>>(out);
}

// round 6
// speedup vs baseline: 2.3160x; 1.2125x over previous
#include <cuda_runtime.h>
#include <cuda_bf16.h>
#include <cstdint>
#include <math.h>

// Problem constants
#define BB 4
#define TT 512
#define DD 512
#define HH 1024
#define VV 50000
#define VPAD 50048             // VV rounded up to 128
#define NTILE (VPAD/128)       // 391 n-tiles in the V GEMM
#define PSPITCH 392            // partial-sum row pitch
#define MROWS (BB*TT)          // 2048
#define G4H (4*HH)             // 4096
#define NB_REC 128             // recurrence CTAs (all resident wave-1)
#define NCHUNK 16              // h broadcast chunks per step (64 cols each)
#define CPC 8                  // CTAs per chunk
#define CNT_TARGET (CPC*32)    // 8 CTAs x 32 lanes release per chunk

// ---------------- device scratch (static; zero-initialized) ------------------
__device__ __align__(256) __nv_bfloat16 g_emb [MROWS*DD];
__device__ __align__(256) __nv_bfloat16 g_Wih0[G4H*DD];
__device__ __align__(256) __nv_bfloat16 g_Wih1[G4H*HH];
__device__ __align__(256) __nv_bfloat16 g_Wout[(size_t)VPAD*HH];  // tail rows stay 0
__device__ __align__(256) float         g_xg  [MROWS*G4H];
__device__ __align__(256) __nv_bfloat16 g_h0  [MROWS*HH];
__device__ __align__(256) __nv_bfloat16 g_h1  [MROWS*HH];
__device__ __align__(256) float         g_hbuf[2*BB*HH];
__device__ __align__(256) int           g_cnt [TT][NCHUNK][32];  // counter @[..][0]
__device__ __align__(256) float         g_psum[(size_t)MROWS*PSPITCH];
__device__ __align__(256) float         g_rowoff[MROWS];

// ---------------- small helpers ----------------------------------------------
__device__ __forceinline__ uint32_t smem_u32(const void* p) {
    return (uint32_t)__cvta_generic_to_shared(p);
}
__device__ __forceinline__ void ldmatrix_x4(uint32_t r[4], uint32_t addr) {
    asm volatile("ldmatrix.sync.aligned.m8n8.x4.shared.b16 {%0,%1,%2,%3}, [%4];"
                 : "=r"(r[0]), "=r"(r[1]), "=r"(r[2]), "=r"(r[3]) : "r"(addr));
}
__device__ __forceinline__ void ldmatrix_x2(uint32_t r[2], uint32_t addr) {
    asm volatile("ldmatrix.sync.aligned.m8n8.x2.shared.b16 {%0,%1}, [%2];"
                 : "=r"(r[0]), "=r"(r[1]) : "r"(addr));
}
__device__ __forceinline__ void mma16816(float d[4], const uint32_t a[4],
                                         const uint32_t b[2], const float c[4]) {
    asm volatile(
        "mma.sync.aligned.m16n8k16.row.col.f32.bf16.bf16.f32 "
        "{%0,%1,%2,%3}, {%4,%5,%6,%7}, {%8,%9}, {%10,%11,%12,%13};"
        : "=f"(d[0]), "=f"(d[1]), "=f"(d[2]), "=f"(d[3])
        : "r"(a[0]), "r"(a[1]), "r"(a[2]), "r"(a[3]),
          "r"(b[0]), "r"(b[1]),
          "f"(c[0]), "f"(c[1]), "f"(c[2]), "f"(c[3]));
}
__device__ __forceinline__ void ffma2(unsigned long long& d,
                                      unsigned long long a, unsigned long long b) {
    asm volatile("fma.rn.f32x2 %0, %1, %2, %0;" : "+l"(d) : "l"(a), "l"(b));
}
__device__ __forceinline__ float f32x2_sum(unsigned long long v) {
    float x, y;
    asm("mov.b64 {%0,%1}, %2;" : "=f"(x), "=f"(y) : "l"(v));
    return x + y;
}
__device__ __forceinline__ void cp_async16(uint32_t saddr, const void* g) {
    asm volatile("cp.async.cg.shared.global [%0], [%1], 16;" :: "r"(saddr), "l"(g));
}
__device__ __forceinline__ void cp_commit() {
    asm volatile("cp.async.commit_group;");
}
__device__ __forceinline__ int ld_acq(const int* p) {
    int v;
    asm volatile("ld.acquire.gpu.global.b32 %0, [%1];" : "=r"(v) : "l"(p) : "memory");
    return v;
}
__device__ __forceinline__ void red_rel_add(int* p) {
    int one = 1;
    asm volatile("red.release.gpu.global.add.s32 [%0], %1;" :: "l"(p), "r"(one) : "memory");
}
__device__ __forceinline__ float tanhapx(float x) {
    float y; asm("tanh.approx.f32 %0, %1;" : "=f"(y) : "f"(x)); return y;
}
__device__ __forceinline__ float sigapx(float x) {
    return fmaf(0.5f, tanhapx(0.5f * x), 0.5f);
}

// ---------------- conversion / gather kernels ---------------------------------
__global__ void f32_to_bf16_k(const float* __restrict__ in,
                              __nv_bfloat16* __restrict__ out, int n4) {
    int i = blockIdx.x * blockDim.x + threadIdx.x;
    if (i >= n4) return;
    float4 v = *((const float4*)in + i);
    __nv_bfloat162 lo = __floats2bfloat162_rn(v.x, v.y);
    __nv_bfloat162 hi = __floats2bfloat162_rn(v.z, v.w);
    uint2 u;
    u.x = *(uint32_t*)&lo; u.y = *(uint32_t*)&hi;
    *((uint2*)out + i) = u;
}

__global__ void gather_embed_k(const int* __restrict__ idx,
                               const float* __restrict__ X) {
    int i = blockIdx.x * blockDim.x + threadIdx.x;   // one float4 each
    if (i >= MROWS * (DD/4)) return;
    int r = i >> 7;             // DD/4 = 128
    int j = i & 127;
    int tok = __ldg(&idx[r]);
    float4 v = *(const float4*)(X + (size_t)tok * DD + j * 4);
    __nv_bfloat162 lo = __floats2bfloat162_rn(v.x, v.y);
    __nv_bfloat162 hi = __floats2bfloat162_rn(v.z, v.w);
    uint2 u; u.x = *(uint32_t*)&lo; u.y = *(uint32_t*)&hi;
    *((uint2*)(g_emb + (size_t)r * DD) + j) = u;
}

// ---------------- bf16 MMA GEMM: C[M,N] = A[M,K] * B[N,K]^T + bias ------------
// CTA tile 128x128, K-tile 64, cp.async 2-stage pipeline, 8 warps (2Mx4N).
// do_sum: also emit per-tile exp-row-sums into psum[row*PSPITCH + blockIdx.y].
#define GPITCH 72
#define GSTAGE (128*GPITCH)
#define GEMM_SMEM (4*GSTAGE*2)      // bytes

__global__ __launch_bounds__(256) void gemm_bf16_k(
    const __nv_bfloat16* __restrict__ A, const __nv_bfloat16* __restrict__ B,
    const float* __restrict__ bias, float* __restrict__ C,
    int M, int N, int K, float* __restrict__ psum, int do_sum)
{
    extern __shared__ __nv_bfloat16 gsm_[];
    __nv_bfloat16* sA = gsm_;                // [2][128][GPITCH]
    __nv_bfloat16* sB = gsm_ + 2*GSTAGE;     // [2][128][GPITCH]

    const int tid  = threadIdx.x;
    const int warp = tid >> 5, lane = tid & 31;
    const int wm = warp & 1, wn = warp >> 1;
    const int m0 = blockIdx.x * 128, n0 = blockIdx.y * 128;

    float acc[4][4][4];
#pragma unroll
    for (int a = 0; a < 4; a++)
#pragma unroll
        for (int b = 0; b < 4; b++)
#pragma unroll
            for (int c = 0; c < 4; c++) acc[a][b][c] = 0.f;

    const int ktiles = K >> 6;

    auto load_stage = [&](int st, int k0) {
#pragma unroll
        for (int i = 0; i < 4; i++) {
            int c   = tid + i * 256;
            int row = c >> 3;
            int col = (c & 7) << 3;
            uint32_t da = smem_u32(sA + st*GSTAGE + row*GPITCH + col);
            cp_async16(da, A + (size_t)(m0 + row) * K + k0 + col);
            uint32_t db = smem_u32(sB + st*GSTAGE + row*GPITCH + col);
            cp_async16(db, B + (size_t)(n0 + row) * K + k0 + col);
        }
    };

    load_stage(0, 0);
    cp_commit();

    for (int kt = 0; kt < ktiles; kt++) {
        if (kt + 1 < ktiles) {
            load_stage((kt + 1) & 1, (kt + 1) << 6);
            cp_commit();
            asm volatile("cp.async.wait_group 1;");
        } else {
            asm volatile("cp.async.wait_group 0;");
        }
        __syncthreads();

        const __nv_bfloat16* cA = sA + (kt & 1) * GSTAGE;
        const __nv_bfloat16* cB = sB + (kt & 1) * GSTAGE;
#pragma unroll
        for (int ks = 0; ks < 4; ks++) {
            uint32_t af[4][4], bf[4][2];
#pragma unroll
            for (int mt = 0; mt < 4; mt++) {
                uint32_t addr = smem_u32(
                    cA + (wm*64 + mt*16 + (lane & 15))*GPITCH
                       + ks*16 + ((lane >> 4) << 3));
                ldmatrix_x4(af[mt], addr);
            }
#pragma unroll
            for (int nt = 0; nt < 4; nt++) {
                uint32_t addr = smem_u32(
                    cB + (wn*32 + nt*8 + (lane & 7))*GPITCH
                       + ks*16 + (((lane >> 3) & 1) << 3));
                ldmatrix_x2(bf[nt], addr);
            }
#pragma unroll
            for (int mt = 0; mt < 4; mt++)
#pragma unroll
                for (int nt = 0; nt < 4; nt++)
                    mma16816(acc[mt][nt], af[mt], bf[nt], acc[mt][nt]);
        }
        __syncthreads();
    }

    // epilogue: write C (+ optional exp-row-sum partials)
    float rs[4][2];
#pragma unroll
    for (int mt = 0; mt < 4; mt++) { rs[mt][0] = 0.f; rs[mt][1] = 0.f; }

#pragma unroll
    for (int mt = 0; mt < 4; mt++)
#pragma unroll
        for (int nt = 0; nt < 4; nt++)
#pragma unroll
            for (int i = 0; i < 4; i++) {
                int row = m0 + wm*64 + mt*16 + (lane >> 2) + ((i >> 1) << 3);
                int col = n0 + wn*32 + nt*8 + ((lane & 3) << 1) + (i & 1);
                if (col < N) {
                    float v = acc[mt][nt][i] + __ldg(&bias[col]);
                    C[(size_t)row * N + col] = v;
                    if (do_sum) rs[mt][i >> 1] += __expf(v);
                }
            }

    if (do_sum) {
        float* ps = (float*)gsm_;            // [4][128] floats, reuse smem
#pragma unroll
        for (int mt = 0; mt < 4; mt++)
#pragma unroll
            for (int ih = 0; ih < 2; ih++) {
                float s = rs[mt][ih];
                s += __shfl_xor_sync(0xffffffffu, s, 1);
                s += __shfl_xor_sync(0xffffffffu, s, 2);
                if ((lane & 3) == 0) {
                    int rloc = wm*64 + mt*16 + (lane >> 2) + ih*8;
                    ps[wn*128 + rloc] = s;
                }
            }
        __syncthreads();
        if (tid < 128) {
            float s = ps[tid] + ps[128 + tid] + ps[256 + tid] + ps[384 + tid];
            psum[(size_t)(m0 + tid) * PSPITCH + blockIdx.y] = s;
        }
    }
}

// ---------------- persistent LSTM recurrence, chunked h exchange --------------
// 128 CTAs x 256 threads; warp ke owns k-slice [128ke,128ke+128), thread row
// r = tid&31 -> gate-row gate*HH + c0 + ci with W in 128 registers.
// Per step: poll 2 chunk counters, stage h per warp, FFMA2 dot, ONE
// __syncthreads, warp0 reduces 8 k-partials + xg, HW-tanh activations,
// publishes h (per-lane red.release, no fence), stores hseq after release.
__global__ __launch_bounds__(256) void lstm_rec_k(
    const float* __restrict__ xg,
    const float* __restrict__ Whh,
    __nv_bfloat16* __restrict__ hseq)
{
    __shared__ __align__(16) float hstage[8][2][4][64];  // [warp][half][b][k]
    __shared__ __align__(16) float part[8*128];          // [k8][row*4+b]
    __shared__ float sxg[2][128];                        // double-buffered xg
    __shared__ float csm[32];

    const int tid  = threadIdx.x;
    const int bk   = blockIdx.x;
    const int c0   = bk * 8;
    const int ke   = tid >> 5;      // warp = k-eighth
    const int r    = tid & 31;      // local gate-row
    const int lane = tid & 31;
    const int gate = r >> 3, ci = r & 7;

    // clear the two counter slots the previous launch left set
    if (bk < NCHUNK && tid == 0) {
        g_cnt[TT-2][bk][0] = 0;
        g_cnt[TT-1][bk][0] = 0;
    }

    // ---- this thread's 128 W_hh weights -> registers (as 64 f32x2) ----
    unsigned long long W[64];
    {
        const float* wsrc = Whh + (size_t)(gate*HH + c0 + ci) * HH + ke * 128;
        union { float4 f; ulonglong2 u; } cv;
#pragma unroll
        for (int i = 0; i < 32; i++) {
            cv.f = __ldg((const float4*)(wsrc + 4*i));
            W[2*i]   = cv.u.x;
            W[2*i+1] = cv.u.y;
        }
    }
    if (tid < 32) csm[tid] = 0.f;

    // xg loader mapping (tid < 128): r2 = gate-row, b2 = batch
    const int r2 = tid >> 2, b2 = tid & 3;
    const float* xgp = xg + (size_t)b2*TT*G4H + (r2 >> 3)*HH + c0 + (r2 & 7);

    __syncthreads();

    for (int t = 0; t < TT; t++) {
        // prefetch the additive xg term into this step's sxg buffer
        if (tid < 128) sxg[t & 1][tid] = __ldg(xgp + (size_t)t * G4H);

        unsigned long long accA[4] = {0ull,0ull,0ull,0ull};
        unsigned long long accB[4] = {0ull,0ull,0ull,0ull};

        if (t > 0) {
            const float* hsrc = g_hbuf + (t & 1) * BB * HH;
#pragma unroll
            for (int half = 0; half < 2; half++) {
                const int ch = 2*ke + half;
                const int* cp = &g_cnt[t-1][ch][0];
                int v;
                do { v = ld_acq(cp); } while (v < CNT_TARGET);

                // stage the 1KB chunk coalesced (2 float4 per lane)
#pragma unroll
                for (int q = 0; q < 2; q++) {
                    int ii = lane + q*32;          // 0..63
                    int b = ii >> 4, j = ii & 15;
                    float4 hv = __ldcg((const float4*)(hsrc + b*HH + ch*64 + 4*j));
                    *(float4*)&hstage[ke][half][b][4*j] = hv;
                }
                __syncwarp();

                // dot over this 64-col chunk, 4 batches (broadcast LDS)
#pragma unroll
                for (int j = 0; j < 16; j++) {
#pragma unroll
                    for (int b = 0; b < 4; b++) {
                        union { float4 f; ulonglong2 u; } hv;
                        hv.f = *(const float4*)&hstage[ke][half][b][4*j];
                        ffma2(accA[b], W[32*half + 2*j],     hv.u.x);
                        ffma2(accB[b], W[32*half + 2*j + 1], hv.u.y);
                    }
                }
            }
            // recycle slot t-2: all CTAs are provably past their t-2 polls
            if (t >= 2 && bk < NCHUNK && tid == 32) g_cnt[t-2][bk][0] = 0;
        }

        float4 ps;
        ps.x = f32x2_sum(accA[0]) + f32x2_sum(accB[0]);
        ps.y = f32x2_sum(accA[1]) + f32x2_sum(accB[1]);
        ps.z = f32x2_sum(accA[2]) + f32x2_sum(accB[2]);
        ps.w = f32x2_sum(accA[3]) + f32x2_sum(accB[3]);
        *(float4*)&part[tid*4] = ps;           // part[ke*128 + r*4 + b]
        __syncthreads();                       // ONLY CTA-wide sync per step

        // warp0: full reduce + activations + publish
        if (tid < 32) {
            int cc = tid >> 2, b = tid & 3;
            float g4[4];
#pragma unroll
            for (int g = 0; g < 4; g++) {
                int rr = g*8 + cc;
                float s = sxg[t & 1][rr*4 + b];
#pragma unroll
                for (int k8 = 0; k8 < 8; k8++) s += part[k8*128 + rr*4 + b];
                g4[g] = s;
            }
            float iv = sigapx(g4[0]);
            float fv = sigapx(g4[1]);
            float gv = tanhapx(g4[2]);
            float ov = sigapx(g4[3]);
            float c = fv * csm[tid] + iv * gv;
            csm[tid] = c;
            float h = ov * tanhapx(c);
            g_hbuf[((t + 1) & 1) * BB * HH + b * HH + c0 + cc] = h;
            red_rel_add(&g_cnt[t][bk >> 3][0]);     // per-lane release (orders own store)
            hseq[(size_t)(b*TT + t) * HH + c0 + cc] = __float2bfloat16(h);
        }
        // Safety of the single sync: warps 1..7 cannot write part[] or consume
        // h for step t+1 before warp0's releases (their polls gate on them), and
        // sxg is double-buffered, so warp0's tail reads are race-free.
    }
}

// ---------------- log-softmax tail ---------------------------------------------
__global__ void rowlog_k(const float* __restrict__ ps) {
    int row  = blockIdx.x * 8 + (threadIdx.x >> 5);
    int lane = threadIdx.x & 31;
    const float* p = ps + (size_t)row * PSPITCH;
    float s = 0.f;
    for (int i = lane; i < PSPITCH; i += 32) s += p[i];   // pad entry is 0
#pragma unroll
    for (int m = 16; m > 0; m >>= 1) s += __shfl_xor_sync(0xffffffffu, s, m);
    if (lane == 0) g_rowoff[row] = logf(s);
}

__global__ void logsm_apply_k(float* __restrict__ C) {
    const int row = blockIdx.y;
    const int i = blockIdx.x * blockDim.x + threadIdx.x;
    if (i >= VV/4) return;
    float4* p = (float4*)(C + (size_t)row * VV);
    float off = __ldg(&g_rowoff[row]);
    float4 v = p[i];
    v.x -= off; v.y -= off; v.z -= off; v.w -= off;
    p[i] = v;
}

// ---------------- launcher ----------------------------------------------------
extern "C" void kernel_launch(void* const* d_in, const int* in_sizes, int n_in,
                              void* d_out, int out_size) {
    const int*   token_idx = (const int*)  d_in[0];
    const float* X     = (const float*)d_in[1];
    const float* W_ih0 = (const float*)d_in[2];
    const float* W_hh0 = (const float*)d_in[3];
    const float* b0    = (const float*)d_in[4];
    const float* W_ih1 = (const float*)d_in[5];
    const float* W_hh1 = (const float*)d_in[6];
    const float* b1    = (const float*)d_in[7];
    const float* W_out = (const float*)d_in[8];
    const float* b_out = (const float*)d_in[9];
    float* out = (float*)d_out;

    cudaFuncSetAttribute(gemm_bf16_k,
                         cudaFuncAttributeMaxDynamicSharedMemorySize,
                         GEMM_SMEM);

    void *p_emb, *p_Wih0, *p_Wih1, *p_Wout, *p_xg, *p_h0, *p_h1, *p_ps;
    cudaGetSymbolAddress(&p_emb,  g_emb);
    cudaGetSymbolAddress(&p_Wih0, g_Wih0);
    cudaGetSymbolAddress(&p_Wih1, g_Wih1);
    cudaGetSymbolAddress(&p_Wout, g_Wout);
    cudaGetSymbolAddress(&p_xg,   g_xg);
    cudaGetSymbolAddress(&p_h0,   g_h0);
    cudaGetSymbolAddress(&p_h1,   g_h1);
    cudaGetSymbolAddress(&p_ps,   g_psum);

    // layer 0
    gather_embed_k<<<(MROWS*(DD/4) + 255)/256, 256>>>(token_idx, X);
    f32_to_bf16_k<<<(G4H*DD/4 + 255)/256, 256>>>(W_ih0, (__nv_bfloat16*)p_Wih0, G4H*DD/4);
    gemm_bf16_k<<<dim3(MROWS/128, G4H/128), 256, GEMM_SMEM>>>(
        (const __nv_bfloat16*)p_emb, (const __nv_bfloat16*)p_Wih0, b0,
        (float*)p_xg, MROWS, G4H, DD, (float*)p_ps, 0);
    lstm_rec_k<<<NB_REC, 256>>>(
        (const float*)p_xg, W_hh0, (__nv_bfloat16*)p_h0);

    // layer 1
    f32_to_bf16_k<<<(G4H*HH/4 + 255)/256, 256>>>(W_ih1, (__nv_bfloat16*)p_Wih1, G4H*HH/4);
    gemm_bf16_k<<<dim3(MROWS/128, G4H/128), 256, GEMM_SMEM>>>(
        (const __nv_bfloat16*)p_h0, (const __nv_bfloat16*)p_Wih1, b1,
        (float*)p_xg, MROWS, G4H, HH, (float*)p_ps, 0);
    lstm_rec_k<<<NB_REC, 256>>>(
        (const float*)p_xg, W_hh1, (__nv_bfloat16*)p_h1);

    // output projection (+ fused exp-row-sum partials) + log-softmax
    f32_to_bf16_k<<<(VV*HH/4 + 255)/256, 256>>>(W_out, (__nv_bfloat16*)p_Wout, VV*HH/4);
    gemm_bf16_k<<<dim3(MROWS/128, NTILE), 256, GEMM_SMEM>>>(
        (const __nv_bfloat16*)p_h1, (const __nv_bfloat16*)p_Wout, b_out,
        out, MROWS, VV, HH, (float*)p_ps, 1);
    rowlog_k<<<MROWS/8, 256>>>((const float*)p_ps);
    logsm_apply_k<<<dim3((VV/4 + 255)/256, MROWS), 256>>>(out);
}

// round 7
// speedup vs baseline: 2.4723x; 1.0675x over previous
#include <cuda_runtime.h>
#include <cuda_bf16.h>
#include <cstdint>
#include <math.h>

// Problem constants
#define BB 4
#define TT 512
#define DD 512
#define HH 1024
#define VV 50000
#define VPAD 50048             // VV rounded up to 128
#define NTILE (VPAD/128)       // 391 n-tiles in the V GEMM
#define PSPITCH 392            // partial-sum row pitch
#define MROWS (BB*TT)          // 2048
#define G4H (4*HH)             // 4096
#define NB_REC 128             // recurrence CTAs (all resident wave-1)
#define NCHUNK 16              // h broadcast chunks per step (64 cols each)
#define CPC 8                  // CTAs per chunk
#define CNT_TARGET (CPC*32)    // 8 CTAs x 32 lanes release per chunk
#define HSP 136                // hstage bf16 row pitch (bank-conflict-free)

// ---------------- device scratch (static; zero-initialized) ------------------
__device__ __align__(256) __nv_bfloat16 g_emb [MROWS*DD];
__device__ __align__(256) __nv_bfloat16 g_Wih0[G4H*DD];
__device__ __align__(256) __nv_bfloat16 g_Wih1[G4H*HH];
__device__ __align__(256) __nv_bfloat16 g_Wout[(size_t)VPAD*HH];  // tail rows stay 0
__device__ __align__(256) float         g_xg  [MROWS*G4H];
__device__ __align__(256) __nv_bfloat16 g_h0  [MROWS*HH];
__device__ __align__(256) __nv_bfloat16 g_h1  [MROWS*HH];
__device__ __align__(256) __nv_bfloat16 g_hbufb[2*BB*HH];         // bf16 h exchange
__device__ __align__(256) int           g_cnt [TT][NCHUNK][32];   // counter @[..][0]
__device__ __align__(256) float         g_psum[(size_t)MROWS*PSPITCH];
__device__ __align__(256) float         g_rowoff[MROWS];

// ---------------- small helpers ----------------------------------------------
__device__ __forceinline__ uint32_t smem_u32(const void* p) {
    return (uint32_t)__cvta_generic_to_shared(p);
}
__device__ __forceinline__ void ldmatrix_x4(uint32_t r[4], uint32_t addr) {
    asm volatile("ldmatrix.sync.aligned.m8n8.x4.shared.b16 {%0,%1,%2,%3}, [%4];"
                 : "=r"(r[0]), "=r"(r[1]), "=r"(r[2]), "=r"(r[3]) : "r"(addr));
}
__device__ __forceinline__ void ldmatrix_x2(uint32_t r[2], uint32_t addr) {
    asm volatile("ldmatrix.sync.aligned.m8n8.x2.shared.b16 {%0,%1}, [%2];"
                 : "=r"(r[0]), "=r"(r[1]) : "r"(addr));
}
__device__ __forceinline__ void mma16816(float d[4], const uint32_t a[4],
                                         const uint32_t b[2], const float c[4]) {
    asm volatile(
        "mma.sync.aligned.m16n8k16.row.col.f32.bf16.bf16.f32 "
        "{%0,%1,%2,%3}, {%4,%5,%6,%7}, {%8,%9}, {%10,%11,%12,%13};"
        : "=f"(d[0]), "=f"(d[1]), "=f"(d[2]), "=f"(d[3])
        : "r"(a[0]), "r"(a[1]), "r"(a[2]), "r"(a[3]),
          "r"(b[0]), "r"(b[1]),
          "f"(c[0]), "f"(c[1]), "f"(c[2]), "f"(c[3]));
}
__device__ __forceinline__ void cp_async16(uint32_t saddr, const void* g) {
    asm volatile("cp.async.cg.shared.global [%0], [%1], 16;" :: "r"(saddr), "l"(g));
}
__device__ __forceinline__ void cp_commit() {
    asm volatile("cp.async.commit_group;");
}
__device__ __forceinline__ int ld_acq(const int* p) {
    int v;
    asm volatile("ld.acquire.gpu.global.b32 %0, [%1];" : "=r"(v) : "l"(p) : "memory");
    return v;
}
__device__ __forceinline__ void red_rel_add(int* p) {
    int one = 1;
    asm volatile("red.release.gpu.global.add.s32 [%0], %1;" :: "l"(p), "r"(one) : "memory");
}
__device__ __forceinline__ float tanhapx(float x) {
    float y; asm("tanh.approx.f32 %0, %1;" : "=f"(y) : "f"(x)); return y;
}
__device__ __forceinline__ float sigapx(float x) {
    return fmaf(0.5f, tanhapx(0.5f * x), 0.5f);
}
__device__ __forceinline__ uint32_t pack_bf2(float x, float y) {
    __nv_bfloat162 b = __floats2bfloat162_rn(x, y);   // .x in low half
    return *(uint32_t*)&b;
}
__device__ __forceinline__ uint32_t lds_u32(uint32_t addr) {
    uint32_t v;
    asm volatile("ld.shared.b32 %0, [%1];" : "=r"(v) : "r"(addr));
    return v;
}

// ---------------- conversion / gather kernels ---------------------------------
__global__ void f32_to_bf16_k(const float* __restrict__ in,
                              __nv_bfloat16* __restrict__ out, int n4) {
    int i = blockIdx.x * blockDim.x + threadIdx.x;
    if (i >= n4) return;
    float4 v = *((const float4*)in + i);
    __nv_bfloat162 lo = __floats2bfloat162_rn(v.x, v.y);
    __nv_bfloat162 hi = __floats2bfloat162_rn(v.z, v.w);
    uint2 u;
    u.x = *(uint32_t*)&lo; u.y = *(uint32_t*)&hi;
    *((uint2*)out + i) = u;
}

__global__ void gather_embed_k(const int* __restrict__ idx,
                               const float* __restrict__ X) {
    int i = blockIdx.x * blockDim.x + threadIdx.x;   // one float4 each
    if (i >= MROWS * (DD/4)) return;
    int r = i >> 7;             // DD/4 = 128
    int j = i & 127;
    int tok = __ldg(&idx[r]);
    float4 v = *(const float4*)(X + (size_t)tok * DD + j * 4);
    __nv_bfloat162 lo = __floats2bfloat162_rn(v.x, v.y);
    __nv_bfloat162 hi = __floats2bfloat162_rn(v.z, v.w);
    uint2 u; u.x = *(uint32_t*)&lo; u.y = *(uint32_t*)&hi;
    *((uint2*)(g_emb + (size_t)r * DD) + j) = u;
}

// ---------------- bf16 MMA GEMM: C[M,N] = A[M,K] * B[N,K]^T + bias ------------
// CTA tile 128x128, K-tile 64, cp.async 2-stage pipeline, 8 warps (2Mx4N).
// do_sum: also emit per-tile exp-row-sums into psum[row*PSPITCH + blockIdx.y].
#define GPITCH 72
#define GSTAGE (128*GPITCH)
#define GEMM_SMEM (4*GSTAGE*2)      // bytes

__global__ __launch_bounds__(256) void gemm_bf16_k(
    const __nv_bfloat16* __restrict__ A, const __nv_bfloat16* __restrict__ B,
    const float* __restrict__ bias, float* __restrict__ C,
    int M, int N, int K, float* __restrict__ psum, int do_sum)
{
    extern __shared__ __nv_bfloat16 gsm_[];
    __nv_bfloat16* sA = gsm_;                // [2][128][GPITCH]
    __nv_bfloat16* sB = gsm_ + 2*GSTAGE;     // [2][128][GPITCH]

    const int tid  = threadIdx.x;
    const int warp = tid >> 5, lane = tid & 31;
    const int wm = warp & 1, wn = warp >> 1;
    const int m0 = blockIdx.x * 128, n0 = blockIdx.y * 128;

    float acc[4][4][4];
#pragma unroll
    for (int a = 0; a < 4; a++)
#pragma unroll
        for (int b = 0; b < 4; b++)
#pragma unroll
            for (int c = 0; c < 4; c++) acc[a][b][c] = 0.f;

    const int ktiles = K >> 6;

    auto load_stage = [&](int st, int k0) {
#pragma unroll
        for (int i = 0; i < 4; i++) {
            int c   = tid + i * 256;
            int row = c >> 3;
            int col = (c & 7) << 3;
            uint32_t da = smem_u32(sA + st*GSTAGE + row*GPITCH + col);
            cp_async16(da, A + (size_t)(m0 + row) * K + k0 + col);
            uint32_t db = smem_u32(sB + st*GSTAGE + row*GPITCH + col);
            cp_async16(db, B + (size_t)(n0 + row) * K + k0 + col);
        }
    };

    load_stage(0, 0);
    cp_commit();

    for (int kt = 0; kt < ktiles; kt++) {
        if (kt + 1 < ktiles) {
            load_stage((kt + 1) & 1, (kt + 1) << 6);
            cp_commit();
            asm volatile("cp.async.wait_group 1;");
        } else {
            asm volatile("cp.async.wait_group 0;");
        }
        __syncthreads();

        const __nv_bfloat16* cA = sA + (kt & 1) * GSTAGE;
        const __nv_bfloat16* cB = sB + (kt & 1) * GSTAGE;
#pragma unroll
        for (int ks = 0; ks < 4; ks++) {
            uint32_t af[4][4], bf[4][2];
#pragma unroll
            for (int mt = 0; mt < 4; mt++) {
                uint32_t addr = smem_u32(
                    cA + (wm*64 + mt*16 + (lane & 15))*GPITCH
                       + ks*16 + ((lane >> 4) << 3));
                ldmatrix_x4(af[mt], addr);
            }
#pragma unroll
            for (int nt = 0; nt < 4; nt++) {
                uint32_t addr = smem_u32(
                    cB + (wn*32 + nt*8 + (lane & 7))*GPITCH
                       + ks*16 + (((lane >> 3) & 1) << 3));
                ldmatrix_x2(bf[nt], addr);
            }
#pragma unroll
            for (int mt = 0; mt < 4; mt++)
#pragma unroll
                for (int nt = 0; nt < 4; nt++)
                    mma16816(acc[mt][nt], af[mt], bf[nt], acc[mt][nt]);
        }
        __syncthreads();
    }

    // epilogue: write C (+ optional exp-row-sum partials)
    float rs[4][2];
#pragma unroll
    for (int mt = 0; mt < 4; mt++) { rs[mt][0] = 0.f; rs[mt][1] = 0.f; }

#pragma unroll
    for (int mt = 0; mt < 4; mt++)
#pragma unroll
        for (int nt = 0; nt < 4; nt++)
#pragma unroll
            for (int i = 0; i < 4; i++) {
                int row = m0 + wm*64 + mt*16 + (lane >> 2) + ((i >> 1) << 3);
                int col = n0 + wn*32 + nt*8 + ((lane & 3) << 1) + (i & 1);
                if (col < N) {
                    float v = acc[mt][nt][i] + __ldg(&bias[col]);
                    C[(size_t)row * N + col] = v;
                    if (do_sum) rs[mt][i >> 1] += __expf(v);
                }
            }

    if (do_sum) {
        float* ps = (float*)gsm_;            // [4][128] floats, reuse smem
#pragma unroll
        for (int mt = 0; mt < 4; mt++)
#pragma unroll
            for (int ih = 0; ih < 2; ih++) {
                float s = rs[mt][ih];
                s += __shfl_xor_sync(0xffffffffu, s, 1);
                s += __shfl_xor_sync(0xffffffffu, s, 2);
                if ((lane & 3) == 0) {
                    int rloc = wm*64 + mt*16 + (lane >> 2) + ih*8;
                    ps[wn*128 + rloc] = s;
                }
            }
        __syncthreads();
        if (tid < 128) {
            float s = ps[tid] + ps[128 + tid] + ps[256 + tid] + ps[384 + tid];
            psum[(size_t)(m0 + tid) * PSPITCH + blockIdx.y] = s;
        }
    }
}

// ---------------- persistent LSTM recurrence, tensor-core dot -----------------
// 128 CTAs x 256 threads. Per CTA, gates = Whh_local[32x1024] @ h[1024x4] via
// mma.m16n8k16 bf16: warp ke owns k-slice [128ke,128ke+128); its A fragments
// (W_hh bf16) live in 64 registers. h exchanged in bf16 via g_hbufb with the
// R6 chunk-counter protocol (2 chunks/warp, 64 cols each, defer-by-2 recycle).
__global__ __launch_bounds__(256) void lstm_rec_k(
    const float* __restrict__ xg,
    const float* __restrict__ Whh,
    __nv_bfloat16* __restrict__ hseq)
{
    __shared__ __align__(16) __nv_bfloat16 hstage[8][4][HSP];  // [warp][b][128]
    __shared__ __align__(16) float part[8*128];                // [k8][lr*4+b]
    __shared__ float sxg[2][128];                              // double-buffered xg
    __shared__ float csm[32];

    const int tid  = threadIdx.x;
    const int bk   = blockIdx.x;
    const int c0   = bk * 8;
    const int ke   = tid >> 5;      // warp = k-eighth
    const int lane = tid & 31;

    // clear the two counter slots the previous launch left set
    if (bk < NCHUNK && tid == 0) {
        g_cnt[TT-2][bk][0] = 0;
        g_cnt[TT-1][bk][0] = 0;
    }

    // ---- preload W_hh A-fragments (m16n8k16 layout), fp32 -> bf16 ----
    // local gate-row lr -> global row (lr>>3)*HH + c0 + (lr&7)
    uint32_t Af[2][8][4];
    {
        const int r0 = lane >> 2;              // 0..7
        const int kc = (lane & 3) * 2;         // 0,2,4,6
#pragma unroll
        for (int mt = 0; mt < 2; mt++) {
#pragma unroll
            for (int kt = 0; kt < 8; kt++) {
                int kg = 128*ke + 16*kt + kc;
                int lrA = 16*mt + r0;          // rows r0, r0+8 within this m-tile
                int lrB = lrA + 8;
                const float* pA = Whh + (size_t)((lrA >> 3)*HH + c0 + (lrA & 7)) * HH + kg;
                const float* pB = Whh + (size_t)((lrB >> 3)*HH + c0 + (lrB & 7)) * HH + kg;
                float2 a0 = __ldg((const float2*)pA);
                float2 a1 = __ldg((const float2*)pB);
                float2 a2 = __ldg((const float2*)(pA + 8));
                float2 a3 = __ldg((const float2*)(pB + 8));
                Af[mt][kt][0] = pack_bf2(a0.x, a0.y);
                Af[mt][kt][1] = pack_bf2(a1.x, a1.y);
                Af[mt][kt][2] = pack_bf2(a2.x, a2.y);
                Af[mt][kt][3] = pack_bf2(a3.x, a3.y);
            }
        }
    }
    if (tid < 32) csm[tid] = 0.f;

    // xg loader mapping (tid < 128): lr = tid>>2, b = tid&3
    const int lrx = tid >> 2, bx = tid & 3;
    const float* xgp = xg + (size_t)bx*TT*G4H + (lrx >> 3)*HH + c0 + (lrx & 7);

    // B-fragment smem read setup: n = lane>>2 (batch; >=4 invalid -> zero)
    const int  bsel  = (lane >> 2) & 3;
    const bool bval  = lane < 16;
    const uint32_t hs_base = smem_u32(&hstage[ke][bsel][0]) + (lane & 3) * 4;

    __syncthreads();

    for (int t = 0; t < TT; t++) {
        // prefetch the additive xg term into this step's sxg buffer
        if (tid < 128) sxg[t & 1][tid] = __ldg(xgp + (size_t)t * G4H);

        float acc0[4] = {0.f,0.f,0.f,0.f};
        float acc1[4] = {0.f,0.f,0.f,0.f};

        if (t > 0) {
            const __nv_bfloat16* hsrc = g_hbufb + (t & 1) * BB * HH;
            const int sb = lane >> 3, sj = (lane & 7) * 8;  // stage mapping
#pragma unroll
            for (int half = 0; half < 2; half++) {
                const int ch = 2*ke + half;
                const int* cp = &g_cnt[t-1][ch][0];
                int v;
                do { v = ld_acq(cp); } while (v < CNT_TARGET);

                // stage 64 cols x 4 batches bf16 (one uint4 per lane)
                uint4 hv = __ldcg((const uint4*)(hsrc + sb*HH + 128*ke + 64*half + sj));
                *(uint4*)&hstage[ke][sb][64*half + sj] = hv;
                __syncwarp();

                // 4 k-tiles of mma over this half
#pragma unroll
                for (int ktl = 0; ktl < 4; ktl++) {
                    uint32_t addr = hs_base + (64*half + 16*ktl) * 2;
                    uint32_t b0 = lds_u32(addr);
                    uint32_t b1 = lds_u32(addr + 16);
                    uint32_t bf[2];
                    bf[0] = bval ? b0 : 0u;
                    bf[1] = bval ? b1 : 0u;
                    mma16816(acc0, Af[0][4*half + ktl], bf, acc0);
                    mma16816(acc1, Af[1][4*half + ktl], bf, acc1);
                }
            }
            // recycle slot t-2: all CTAs are provably past their t-2 polls
            if (t >= 2 && bk < NCHUNK && tid == 32) g_cnt[t-2][bk][0] = 0;
        }

        // store partials: acc cols n=(lane&3)*2+{0,1}; only n<4 lanes valid
        if ((lane & 3) < 2) {
            int r0 = lane >> 2, bc = (lane & 3) * 2;
            *(float2*)&part[ke*128 + (r0     )*4 + bc] = make_float2(acc0[0], acc0[1]);
            *(float2*)&part[ke*128 + (r0 +  8)*4 + bc] = make_float2(acc0[2], acc0[3]);
            *(float2*)&part[ke*128 + (r0 + 16)*4 + bc] = make_float2(acc1[0], acc1[1]);
            *(float2*)&part[ke*128 + (r0 + 24)*4 + bc] = make_float2(acc1[2], acc1[3]);
        }
        __syncthreads();                       // ONLY CTA-wide sync per step

        // warp0: reduce 8 k-partials + xg, activations, publish
        if (tid < 32) {
            int cc = tid >> 2, b = tid & 3;
            float g4[4];
#pragma unroll
            for (int g = 0; g < 4; g++) {
                int rr = g*8 + cc;
                float s = sxg[t & 1][rr*4 + b];
#pragma unroll
                for (int k8 = 0; k8 < 8; k8++) s += part[k8*128 + rr*4 + b];
                g4[g] = s;
            }
            float iv = sigapx(g4[0]);
            float fv = sigapx(g4[1]);
            float gv = tanhapx(g4[2]);
            float ov = sigapx(g4[3]);
            float c = fv * csm[tid] + iv * gv;
            csm[tid] = c;
            float h = ov * tanhapx(c);
            __nv_bfloat16 hb = __float2bfloat16(h);
            g_hbufb[((t + 1) & 1) * BB * HH + b * HH + c0 + cc] = hb;
            red_rel_add(&g_cnt[t][bk >> 3][0]);   // per-lane release (orders own store)
            hseq[(size_t)(b*TT + t) * HH + c0 + cc] = hb;
        }
        // single-sync safety: warps can't write part[]/hstage for t+1 before
        // their t polls, which gate on warp0's releases; sxg is double-buffered.
    }
}

// ---------------- log-softmax tail ---------------------------------------------
__global__ void rowlog_k(const float* __restrict__ ps) {
    int row  = blockIdx.x * 8 + (threadIdx.x >> 5);
    int lane = threadIdx.x & 31;
    const float* p = ps + (size_t)row * PSPITCH;
    float s = 0.f;
    for (int i = lane; i < PSPITCH; i += 32) s += p[i];   // pad entry is 0
#pragma unroll
    for (int m = 16; m > 0; m >>= 1) s += __shfl_xor_sync(0xffffffffu, s, m);
    if (lane == 0) g_rowoff[row] = logf(s);
}

__global__ void logsm_apply_k(float* __restrict__ C) {
    const int row = blockIdx.y;
    const int i = blockIdx.x * blockDim.x + threadIdx.x;
    if (i >= VV/4) return;
    float4* p = (float4*)(C + (size_t)row * VV);
    float off = __ldg(&g_rowoff[row]);
    float4 v = p[i];
    v.x -= off; v.y -= off; v.z -= off; v.w -= off;
    p[i] = v;
}

// ---------------- launcher ----------------------------------------------------
extern "C" void kernel_launch(void* const* d_in, const int* in_sizes, int n_in,
                              void* d_out, int out_size) {
    const int*   token_idx = (const int*)  d_in[0];
    const float* X     = (const float*)d_in[1];
    const float* W_ih0 = (const float*)d_in[2];
    const float* W_hh0 = (const float*)d_in[3];
    const float* b0    = (const float*)d_in[4];
    const float* W_ih1 = (const float*)d_in[5];
    const float* W_hh1 = (const float*)d_in[6];
    const float* b1    = (const float*)d_in[7];
    const float* W_out = (const float*)d_in[8];
    const float* b_out = (const float*)d_in[9];
    float* out = (float*)d_out;

    cudaFuncSetAttribute(gemm_bf16_k,
                         cudaFuncAttributeMaxDynamicSharedMemorySize,
                         GEMM_SMEM);

    void *p_emb, *p_Wih0, *p_Wih1, *p_Wout, *p_xg, *p_h0, *p_h1, *p_ps;
    cudaGetSymbolAddress(&p_emb,  g_emb);
    cudaGetSymbolAddress(&p_Wih0, g_Wih0);
    cudaGetSymbolAddress(&p_Wih1, g_Wih1);
    cudaGetSymbolAddress(&p_Wout, g_Wout);
    cudaGetSymbolAddress(&p_xg,   g_xg);
    cudaGetSymbolAddress(&p_h0,   g_h0);
    cudaGetSymbolAddress(&p_h1,   g_h1);
    cudaGetSymbolAddress(&p_ps,   g_psum);

    // layer 0
    gather_embed_k<<<(MROWS*(DD/4) + 255)/256, 256>>>(token_idx, X);
    f32_to_bf16_k<<<(G4H*DD/4 + 255)/256, 256>>>(W_ih0, (__nv_bfloat16*)p_Wih0, G4H*DD/4);
    gemm_bf16_k<<<dim3(MROWS/128, G4H/128), 256, GEMM_SMEM>>>(
        (const __nv_bfloat16*)p_emb, (const __nv_bfloat16*)p_Wih0, b0,
        (float*)p_xg, MROWS, G4H, DD, (float*)p_ps, 0);
    lstm_rec_k<<<NB_REC, 256>>>(
        (const float*)p_xg, W_hh0, (__nv_bfloat16*)p_h0);

    // layer 1
    f32_to_bf16_k<<<(G4H*HH/4 + 255)/256, 256>>>(W_ih1, (__nv_bfloat16*)p_Wih1, G4H*HH/4);
    gemm_bf16_k<<<dim3(MROWS/128, G4H/128), 256, GEMM_SMEM>>>(
        (const __nv_bfloat16*)p_h0, (const __nv_bfloat16*)p_Wih1, b1,
        (float*)p_xg, MROWS, G4H, HH, (float*)p_ps, 0);
    lstm_rec_k<<<NB_REC, 256>>>(
        (const float*)p_xg, W_hh1, (__nv_bfloat16*)p_h1);

    // output projection (+ fused exp-row-sum partials) + log-softmax
    f32_to_bf16_k<<<(VV*HH/4 + 255)/256, 256>>>(W_out, (__nv_bfloat16*)p_Wout, VV*HH/4);
    gemm_bf16_k<<<dim3(MROWS/128, NTILE), 256, GEMM_SMEM>>>(
        (const __nv_bfloat16*)p_h1, (const __nv_bfloat16*)p_Wout, b_out,
        out, MROWS, VV, HH, (float*)p_ps, 1);
    rowlog_k<<<MROWS/8, 256>>>((const float*)p_ps);
    logsm_apply_k<<<dim3((VV/4 + 255)/256, MROWS), 256>>>(out);
}

// round 9
// speedup vs baseline: 2.7693x; 1.1201x over previous
#include <cuda_runtime.h>
#include <cuda_bf16.h>
#include <cstdint>
#include <math.h>

// Problem constants
#define BB 4
#define TT 512
#define DD 512
#define HH 1024
#define VV 50000
#define VPAD 50048             // VV rounded up to 128
#define NTILE (VPAD/128)       // 391 n-tiles in the V GEMM
#define PSPITCH 392            // partial-sum row pitch
#define MROWS (BB*TT)          // 2048
#define G4H (4*HH)             // 4096
#define NB_REC 128             // recurrence CTAs (all resident wave-1)
#define NCHUNK 16              // h broadcast chunks per step (64 cols each)
#define CPC 8                  // CTAs per chunk
#define CNT_TARGET (CPC*32)    // 8 CTAs x 32 lanes release per chunk
#define HSP 136                // hstage bf16 row pitch (bank-conflict-light)

// ---------------- device scratch (static; zero-initialized) ------------------
__device__ __align__(256) __nv_bfloat16 g_emb [MROWS*DD];
__device__ __align__(256) __nv_bfloat16 g_Wih0[G4H*DD];
__device__ __align__(256) __nv_bfloat16 g_Wout[(size_t)VPAD*HH];  // tail rows stay 0
__device__ __align__(256) float         g_xg  [MROWS*G4H];
__device__ __align__(256) __nv_bfloat16 g_h1  [MROWS*HH];
__device__ __align__(256) __nv_bfloat16 g_h0buf[2*BB*HH];         // bf16 h0 exchange
__device__ __align__(256) __nv_bfloat16 g_h1buf[2*BB*HH];         // bf16 h1 exchange
__device__ __align__(256) int           g_cnt0[TT][NCHUNK][32];   // counter @[..][0]
__device__ __align__(256) int           g_cnt1[TT][NCHUNK][32];
__device__ __align__(256) float         g_psum[(size_t)MROWS*PSPITCH];
__device__ __align__(256) float         g_rowoff[MROWS];

// ---------------- small helpers ----------------------------------------------
__device__ __forceinline__ uint32_t smem_u32(const void* p) {
    return (uint32_t)__cvta_generic_to_shared(p);
}
__device__ __forceinline__ void ldmatrix_x4(uint32_t r[4], uint32_t addr) {
    asm volatile("ldmatrix.sync.aligned.m8n8.x4.shared.b16 {%0,%1,%2,%3}, [%4];"
                 : "=r"(r[0]), "=r"(r[1]), "=r"(r[2]), "=r"(r[3]) : "r"(addr));
}
__device__ __forceinline__ void ldmatrix_x2(uint32_t r[2], uint32_t addr) {
    asm volatile("ldmatrix.sync.aligned.m8n8.x2.shared.b16 {%0,%1}, [%2];"
                 : "=r"(r[0]), "=r"(r[1]) : "r"(addr));
}
__device__ __forceinline__ void mma16816(float d[4], const uint32_t a[4],
                                         const uint32_t b[2], const float c[4]) {
    asm volatile(
        "mma.sync.aligned.m16n8k16.row.col.f32.bf16.bf16.f32 "
        "{%0,%1,%2,%3}, {%4,%5,%6,%7}, {%8,%9}, {%10,%11,%12,%13};"
        : "=f"(d[0]), "=f"(d[1]), "=f"(d[2]), "=f"(d[3])
        : "r"(a[0]), "r"(a[1]), "r"(a[2]), "r"(a[3]),
          "r"(b[0]), "r"(b[1]),
          "f"(c[0]), "f"(c[1]), "f"(c[2]), "f"(c[3]));
}
__device__ __forceinline__ void cp_async16(uint32_t saddr, const void* g) {
    asm volatile("cp.async.cg.shared.global [%0], [%1], 16;" :: "r"(saddr), "l"(g));
}
__device__ __forceinline__ void cp_commit() {
    asm volatile("cp.async.commit_group;");
}
__device__ __forceinline__ int ld_acq(const int* p) {
    int v;
    asm volatile("ld.acquire.gpu.global.b32 %0, [%1];" : "=r"(v) : "l"(p) : "memory");
    return v;
}
__device__ __forceinline__ void red_rel_add(int* p) {
    int one = 1;
    asm volatile("red.release.gpu.global.add.s32 [%0], %1;" :: "l"(p), "r"(one) : "memory");
}
__device__ __forceinline__ float tanhapx(float x) {
    float y; asm("tanh.approx.f32 %0, %1;" : "=f"(y) : "f"(x)); return y;
}
__device__ __forceinline__ float sigapx(float x) {
    return fmaf(0.5f, tanhapx(0.5f * x), 0.5f);
}
__device__ __forceinline__ uint32_t pack_bf2(float x, float y) {
    __nv_bfloat162 b = __floats2bfloat162_rn(x, y);   // .x in low half
    return *(uint32_t*)&b;
}
__device__ __forceinline__ uint32_t lds_u32(uint32_t addr) {
    uint32_t v;
    asm volatile("ld.shared.b32 %0, [%1];" : "=r"(v) : "r"(addr));
    return v;
}

// ---------------- conversion / gather kernels ---------------------------------
__global__ void f32_to_bf16_k(const float* __restrict__ in,
                              __nv_bfloat16* __restrict__ out, int n4) {
    int i = blockIdx.x * blockDim.x + threadIdx.x;
    if (i >= n4) return;
    float4 v = *((const float4*)in + i);
    __nv_bfloat162 lo = __floats2bfloat162_rn(v.x, v.y);
    __nv_bfloat162 hi = __floats2bfloat162_rn(v.z, v.w);
    uint2 u;
    u.x = *(uint32_t*)&lo; u.y = *(uint32_t*)&hi;
    *((uint2*)out + i) = u;
}

__global__ void gather_embed_k(const int* __restrict__ idx,
                               const float* __restrict__ X) {
    int i = blockIdx.x * blockDim.x + threadIdx.x;   // one float4 each
    if (i >= MROWS * (DD/4)) return;
    int r = i >> 7;             // DD/4 = 128
    int j = i & 127;
    int tok = __ldg(&idx[r]);
    float4 v = *(const float4*)(X + (size_t)tok * DD + j * 4);
    __nv_bfloat162 lo = __floats2bfloat162_rn(v.x, v.y);
    __nv_bfloat162 hi = __floats2bfloat162_rn(v.z, v.w);
    uint2 u; u.x = *(uint32_t*)&lo; u.y = *(uint32_t*)&hi;
    *((uint2*)(g_emb + (size_t)r * DD) + j) = u;
}

// ---------------- bf16 MMA GEMM: C[M,N] = A[M,K] * B[N,K]^T + bias ------------
#define GPITCH 72
#define GSTAGE (128*GPITCH)
#define GEMM_SMEM (4*GSTAGE*2)      // bytes

__global__ __launch_bounds__(256) void gemm_bf16_k(
    const __nv_bfloat16* __restrict__ A, const __nv_bfloat16* __restrict__ B,
    const float* __restrict__ bias, float* __restrict__ C,
    int M, int N, int K, float* __restrict__ psum, int do_sum)
{
    extern __shared__ __nv_bfloat16 gsm_[];
    __nv_bfloat16* sA = gsm_;                // [2][128][GPITCH]
    __nv_bfloat16* sB = gsm_ + 2*GSTAGE;     // [2][128][GPITCH]

    const int tid  = threadIdx.x;
    const int warp = tid >> 5, lane = tid & 31;
    const int wm = warp & 1, wn = warp >> 1;
    const int m0 = blockIdx.x * 128, n0 = blockIdx.y * 128;

    float acc[4][4][4];
#pragma unroll
    for (int a = 0; a < 4; a++)
#pragma unroll
        for (int b = 0; b < 4; b++)
#pragma unroll
            for (int c = 0; c < 4; c++) acc[a][b][c] = 0.f;

    const int ktiles = K >> 6;

    auto load_stage = [&](int st, int k0) {
#pragma unroll
        for (int i = 0; i < 4; i++) {
            int c   = tid + i * 256;
            int row = c >> 3;
            int col = (c & 7) << 3;
            uint32_t da = smem_u32(sA + st*GSTAGE + row*GPITCH + col);
            cp_async16(da, A + (size_t)(m0 + row) * K + k0 + col);
            uint32_t db = smem_u32(sB + st*GSTAGE + row*GPITCH + col);
            cp_async16(db, B + (size_t)(n0 + row) * K + k0 + col);
        }
    };

    load_stage(0, 0);
    cp_commit();

    for (int kt = 0; kt < ktiles; kt++) {
        if (kt + 1 < ktiles) {
            load_stage((kt + 1) & 1, (kt + 1) << 6);
            cp_commit();
            asm volatile("cp.async.wait_group 1;");
        } else {
            asm volatile("cp.async.wait_group 0;");
        }
        __syncthreads();

        const __nv_bfloat16* cA = sA + (kt & 1) * GSTAGE;
        const __nv_bfloat16* cB = sB + (kt & 1) * GSTAGE;
#pragma unroll
        for (int ks = 0; ks < 4; ks++) {
            uint32_t af[4][4], bf[4][2];
#pragma unroll
            for (int mt = 0; mt < 4; mt++) {
                uint32_t addr = smem_u32(
                    cA + (wm*64 + mt*16 + (lane & 15))*GPITCH
                       + ks*16 + ((lane >> 4) << 3));
                ldmatrix_x4(af[mt], addr);
            }
#pragma unroll
            for (int nt = 0; nt < 4; nt++) {
                uint32_t addr = smem_u32(
                    cB + (wn*32 + nt*8 + (lane & 7))*GPITCH
                       + ks*16 + (((lane >> 3) & 1) << 3));
                ldmatrix_x2(bf[nt], addr);
            }
#pragma unroll
            for (int mt = 0; mt < 4; mt++)
#pragma unroll
                for (int nt = 0; nt < 4; nt++)
                    mma16816(acc[mt][nt], af[mt], bf[nt], acc[mt][nt]);
        }
        __syncthreads();
    }

    // epilogue: write C (+ optional exp-row-sum partials)
    float rs[4][2];
#pragma unroll
    for (int mt = 0; mt < 4; mt++) { rs[mt][0] = 0.f; rs[mt][1] = 0.f; }

#pragma unroll
    for (int mt = 0; mt < 4; mt++)
#pragma unroll
        for (int nt = 0; nt < 4; nt++)
#pragma unroll
            for (int i = 0; i < 4; i++) {
                int row = m0 + wm*64 + mt*16 + (lane >> 2) + ((i >> 1) << 3);
                int col = n0 + wn*32 + nt*8 + ((lane & 3) << 1) + (i & 1);
                if (col < N) {
                    float v = acc[mt][nt][i] + __ldg(&bias[col]);
                    C[(size_t)row * N + col] = v;
                    if (do_sum) rs[mt][i >> 1] += __expf(v);
                }
            }

    if (do_sum) {
        float* ps = (float*)gsm_;            // [4][128] floats, reuse smem
#pragma unroll
        for (int mt = 0; mt < 4; mt++)
#pragma unroll
            for (int ih = 0; ih < 2; ih++) {
                float s = rs[mt][ih];
                s += __shfl_xor_sync(0xffffffffu, s, 1);
                s += __shfl_xor_sync(0xffffffffu, s, 2);
                if ((lane & 3) == 0) {
                    int rloc = wm*64 + mt*16 + (lane >> 2) + ih*8;
                    ps[wn*128 + rloc] = s;
                }
            }
        __syncthreads();
        if (tid < 128) {
            float s = ps[tid] + ps[128 + tid] + ps[256 + tid] + ps[384 + tid];
            psum[(size_t)(m0 + tid) * PSPITCH + blockIdx.y] = s;
        }
    }
}

// ---------------- fused 2-layer persistent LSTM -------------------------------
// 128 CTAs x 256 threads, TT+1 pipelined waves. Wave s computes layer0 step s
// (if s<TT) and layer1 step s-1 (if s>=1); both consume data published in
// wave s-1. Per CTA: 32 gate rows per layer; warp ke owns k-slice
// [128ke,128ke+128) with register A-fragments for W_hh0, W_ih1, W_hh1.
// W_ih1@h0 and W_hh1@h1 share one accumulator (acc1). Warp0 tail publishes
// h0 -> cnt0; warp1 tail publishes h1 -> cnt1 (chunk counters, defer-2 recycle).
__global__ __launch_bounds__(256) void lstm_fused_k(
    const float* __restrict__ xg,
    const float* __restrict__ Whh0,
    const float* __restrict__ Wih1,
    const float* __restrict__ b1,
    const float* __restrict__ Whh1,
    __nv_bfloat16* __restrict__ hseq1)
{
    __shared__ __align__(16) __nv_bfloat16 hst0[8][4][HSP];  // staged h0 per warp
    __shared__ __align__(16) __nv_bfloat16 hst1[8][4][HSP];  // staged h1 per warp
    __shared__ __align__(16) float part0[8*128];
    __shared__ __align__(16) float part1[8*128];
    __shared__ float sxg[2][128];
    __shared__ float csm0[32], csm1[32];

    const int tid  = threadIdx.x;
    const int bk   = blockIdx.x;
    const int c0   = bk * 8;
    const int ke   = tid >> 5;
    const int lane = tid & 31;

    // clear counter slots a previous replay left set
    if (bk < NCHUNK && tid == 0) {
        g_cnt0[TT-2][bk][0] = 0; g_cnt0[TT-1][bk][0] = 0;
        g_cnt1[TT-2][bk][0] = 0; g_cnt1[TT-1][bk][0] = 0;
    }

    // ---- preload 3 weight sets as m16n8k16 A-fragments (fp32 -> bf16) ----
    uint32_t A0[2][8][4], Ai[2][8][4], A1[2][8][4];
    {
        const int r0 = lane >> 2;
        const int kc = (lane & 3) * 2;
#pragma unroll
        for (int mt = 0; mt < 2; mt++) {
#pragma unroll
            for (int kt = 0; kt < 8; kt++) {
                int kg = 128*ke + 16*kt + kc;
                int lrA = 16*mt + r0, lrB = lrA + 8;
                size_t oA = (size_t)((lrA >> 3)*HH + c0 + (lrA & 7)) * HH + kg;
                size_t oB = (size_t)((lrB >> 3)*HH + c0 + (lrB & 7)) * HH + kg;
#define LOADFRAG(W, F) { \
                float2 a0 = __ldg((const float2*)(W + oA)); \
                float2 a1 = __ldg((const float2*)(W + oB)); \
                float2 a2 = __ldg((const float2*)(W + oA + 8)); \
                float2 a3 = __ldg((const float2*)(W + oB + 8)); \
                F[mt][kt][0] = pack_bf2(a0.x, a0.y); \
                F[mt][kt][1] = pack_bf2(a1.x, a1.y); \
                F[mt][kt][2] = pack_bf2(a2.x, a2.y); \
                F[mt][kt][3] = pack_bf2(a3.x, a3.y); }
                LOADFRAG(Whh0, A0)
                LOADFRAG(Wih1, Ai)
                LOADFRAG(Whh1, A1)
#undef LOADFRAG
            }
        }
    }
    if (tid < 32) { csm0[tid] = 0.f; csm1[tid] = 0.f; }

    // warp1 tail: bias b1 for its 4 gates (cell cc = lane>>2)
    float b1v[4];
    {
        int cc = lane >> 2;
#pragma unroll
        for (int g = 0; g < 4; g++) b1v[g] = __ldg(&b1[g*HH + c0 + cc]);
    }

    // xg loader mapping (tid < 128): lr = tid>>2, b = tid&3
    const int lrx = tid >> 2, bx = tid & 3;
    const float* xgp = xg + (size_t)bx*TT*G4H + (lrx >> 3)*HH + c0 + (lrx & 7);

    // B-fragment read setup: n = lane>>2 (batch; >=4 -> zero)
    const int  bsel = (lane >> 2) & 3;
    const bool bval = lane < 16;
    const uint32_t hb0 = smem_u32(&hst0[ke][bsel][0]) + (lane & 3) * 4;
    const uint32_t hb1 = smem_u32(&hst1[ke][bsel][0]) + (lane & 3) * 4;
    const int sb = lane >> 3, sj = (lane & 7) * 8;   // stage store mapping

    __syncthreads();

    for (int s = 0; s <= TT; s++) {
        if (tid < 128 && s < TT) sxg[s & 1][tid] = __ldg(xgp + (size_t)s * G4H);

        float acc0[8] = {0,0,0,0,0,0,0,0};   // layer0 gates (2 m-tiles x 4)
        float acc1[8] = {0,0,0,0,0,0,0,0};   // layer1 gates

        if (s > 0) {
            const __nv_bfloat16* h0src = g_h0buf + (s & 1) * BB * HH;
            const __nv_bfloat16* h1src = g_h1buf + (s & 1) * BB * HH;
#pragma unroll
            for (int half = 0; half < 2; half++) {
                const int ch = 2*ke + half;
                // --- h0 chunk: feeds W_hh0 (acc0) and W_ih1 (acc1) ---
                {
                    const int* cp = &g_cnt0[s-1][ch][0];
                    int v; do { v = ld_acq(cp); } while (v < CNT_TARGET);
                    uint4 hv = __ldcg((const uint4*)(h0src + sb*HH + 128*ke + 64*half + sj));
                    *(uint4*)&hst0[ke][sb][64*half + sj] = hv;
                    __syncwarp();
#pragma unroll
                    for (int ktl = 0; ktl < 4; ktl++) {
                        uint32_t addr = hb0 + (64*half + 16*ktl) * 2;
                        uint32_t bf[2];
                        bf[0] = bval ? lds_u32(addr)      : 0u;
                        bf[1] = bval ? lds_u32(addr + 16) : 0u;
                        mma16816(acc0,     A0[0][4*half + ktl], bf, acc0);
                        mma16816(acc0 + 4, A0[1][4*half + ktl], bf, acc0 + 4);
                        mma16816(acc1,     Ai[0][4*half + ktl], bf, acc1);
                        mma16816(acc1 + 4, Ai[1][4*half + ktl], bf, acc1 + 4);
                    }
                }
                // --- h1 chunk: feeds W_hh1 (acc1) ---
                {
                    const int* cp = &g_cnt1[s-1][ch][0];
                    int v; do { v = ld_acq(cp); } while (v < CNT_TARGET);
                    uint4 hv = __ldcg((const uint4*)(h1src + sb*HH + 128*ke + 64*half + sj));
                    *(uint4*)&hst1[ke][sb][64*half + sj] = hv;
                    __syncwarp();
#pragma unroll
                    for (int ktl = 0; ktl < 4; ktl++) {
                        uint32_t addr = hb1 + (64*half + 16*ktl) * 2;
                        uint32_t bf[2];
                        bf[0] = bval ? lds_u32(addr)      : 0u;
                        bf[1] = bval ? lds_u32(addr + 16) : 0u;
                        mma16816(acc1,     A1[0][4*half + ktl], bf, acc1);
                        mma16816(acc1 + 4, A1[1][4*half + ktl], bf, acc1 + 4);
                    }
                }
            }
            if (s >= 2 && bk < NCHUNK && tid == 32) {
                g_cnt0[s-2][bk][0] = 0;
                g_cnt1[s-2][bk][0] = 0;
            }
        }

        // store partials (acc cols n = (lane&3)*2 + {0,1}; n<4 lanes valid)
        if ((lane & 3) < 2) {
            int r0 = lane >> 2, bc = (lane & 3) * 2;
#pragma unroll
            for (int mt = 0; mt < 2; mt++) {
                *(float2*)&part0[ke*128 + (mt*16 + r0    )*4 + bc] = make_float2(acc0[mt*4+0], acc0[mt*4+1]);
                *(float2*)&part0[ke*128 + (mt*16 + r0 + 8)*4 + bc] = make_float2(acc0[mt*4+2], acc0[mt*4+3]);
                *(float2*)&part1[ke*128 + (mt*16 + r0    )*4 + bc] = make_float2(acc1[mt*4+0], acc1[mt*4+1]);
                *(float2*)&part1[ke*128 + (mt*16 + r0 + 8)*4 + bc] = make_float2(acc1[mt*4+2], acc1[mt*4+3]);
            }
        }
        __syncthreads();                     // the ONLY CTA-wide sync per wave

        if (tid < 32 && s < TT) {
            // warp0: layer0 tail -> h0[s]
            int cc = tid >> 2, b = tid & 3;
            float g4[4];
#pragma unroll
            for (int g = 0; g < 4; g++) {
                int rr = g*8 + cc;
                float sum = sxg[s & 1][rr*4 + b];
#pragma unroll
                for (int k8 = 0; k8 < 8; k8++) sum += part0[k8*128 + rr*4 + b];
                g4[g] = sum;
            }
            float iv = sigapx(g4[0]), fv = sigapx(g4[1]);
            float gv = tanhapx(g4[2]), ov = sigapx(g4[3]);
            float c = fv * csm0[tid] + iv * gv;
            csm0[tid] = c;
            float h = ov * tanhapx(c);
            g_h0buf[((s + 1) & 1) * BB * HH + b * HH + c0 + cc] = __float2bfloat16(h);
            red_rel_add(&g_cnt0[s][bk >> 3][0]);
        } else if (tid >= 32 && tid < 64) {
            // warp1: layer1 tail -> h1[s-1]
            int cc = lane >> 2, b = lane & 3;
            if (s > 0) {
                float g4[4];
#pragma unroll
                for (int g = 0; g < 4; g++) {
                    int rr = g*8 + cc;
                    float sum = b1v[g];
#pragma unroll
                    for (int k8 = 0; k8 < 8; k8++) sum += part1[k8*128 + rr*4 + b];
                    g4[g] = sum;
                }
                float iv = sigapx(g4[0]), fv = sigapx(g4[1]);
                float gv = tanhapx(g4[2]), ov = sigapx(g4[3]);
                float c = fv * csm1[lane] + iv * gv;
                csm1[lane] = c;
                float h = ov * tanhapx(c);
                __nv_bfloat16 hb = __float2bfloat16(h);
                g_h1buf[((s + 1) & 1) * BB * HH + b * HH + c0 + cc] = hb;
                if (s < TT) red_rel_add(&g_cnt1[s][bk >> 3][0]);
                hseq1[(size_t)(b*TT + (s-1)) * HH + c0 + cc] = hb;
            } else {
                // s==0: publish h1[-1] = 0 (overwrite replay-stale buffer)
                g_h1buf[1 * BB * HH + b * HH + c0 + cc] = __float2bfloat16(0.f);
                red_rel_add(&g_cnt1[0][bk >> 3][0]);
            }
        }
        // single-sync safety: no warp can write part*/hst* for wave s+1 before
        // its s polls succeed, which gate on warp0/warp1 releases of wave s;
        // sxg is double-buffered.
    }
}

// ---------------- log-softmax tail ---------------------------------------------
__global__ void rowlog_k(const float* __restrict__ ps) {
    int row  = blockIdx.x * 8 + (threadIdx.x >> 5);
    int lane = threadIdx.x & 31;
    const float* p = ps + (size_t)row * PSPITCH;
    float s = 0.f;
    for (int i = lane; i < PSPITCH; i += 32) s += p[i];   // pad entry is 0
#pragma unroll
    for (int m = 16; m > 0; m >>= 1) s += __shfl_xor_sync(0xffffffffu, s, m);
    if (lane == 0) g_rowoff[row] = logf(s);
}

__global__ void logsm_apply_k(float* __restrict__ C) {
    const int row = blockIdx.y;
    const int i = blockIdx.x * blockDim.x + threadIdx.x;
    if (i >= VV/4) return;
    float4* p = (float4*)(C + (size_t)row * VV);
    float off = __ldg(&g_rowoff[row]);
    float4 v = p[i];
    v.x -= off; v.y -= off; v.z -= off; v.w -= off;
    p[i] = v;
}

// ---------------- launcher ----------------------------------------------------
extern "C" void kernel_launch(void* const* d_in, const int* in_sizes, int n_in,
                              void* d_out, int out_size) {
    const int*   token_idx = (const int*)  d_in[0];
    const float* X     = (const float*)d_in[1];
    const float* W_ih0 = (const float*)d_in[2];
    const float* W_hh0 = (const float*)d_in[3];
    const float* b0    = (const float*)d_in[4];
    const float* W_ih1 = (const float*)d_in[5];
    const float* W_hh1 = (const float*)d_in[6];
    const float* b1    = (const float*)d_in[7];
    const float* W_out = (const float*)d_in[8];
    const float* b_out = (const float*)d_in[9];
    float* out = (float*)d_out;

    cudaFuncSetAttribute(gemm_bf16_k,
                         cudaFuncAttributeMaxDynamicSharedMemorySize,
                         GEMM_SMEM);

    void *p_emb, *p_Wih0, *p_Wout, *p_xg, *p_h1, *p_ps;
    cudaGetSymbolAddress(&p_emb,  g_emb);
    cudaGetSymbolAddress(&p_Wih0, g_Wih0);
    cudaGetSymbolAddress(&p_Wout, g_Wout);
    cudaGetSymbolAddress(&p_xg,   g_xg);
    cudaGetSymbolAddress(&p_h1,   g_h1);
    cudaGetSymbolAddress(&p_ps,   g_psum);

    // layer-0 input GEMM inputs
    gather_embed_k<<<(MROWS*(DD/4) + 255)/256, 256>>>(token_idx, X);
    f32_to_bf16_k<<<(G4H*DD/4 + 255)/256, 256>>>(W_ih0, (__nv_bfloat16*)p_Wih0, G4H*DD/4);
    // start the big W_out conversion early (independent of everything else)
    f32_to_bf16_k<<<(VV*HH/4 + 255)/256, 256>>>(W_out, (__nv_bfloat16*)p_Wout, VV*HH/4);

    gemm_bf16_k<<<dim3(MROWS/128, G4H/128), 256, GEMM_SMEM>>>(
        (const __nv_bfloat16*)p_emb, (const __nv_bfloat16*)p_Wih0, b0,
        (float*)p_xg, MROWS, G4H, DD, (float*)p_ps, 0);

    // fused 2-layer recurrence (layer-1 input GEMM folded in)
    lstm_fused_k<<<NB_REC, 256>>>(
        (const float*)p_xg, W_hh0, W_ih1, b1, W_hh1, (__nv_bfloat16*)p_h1);

    // output projection (+ fused exp-row-sum partials) + log-softmax
    gemm_bf16_k<<<dim3(MROWS/128, NTILE), 256, GEMM_SMEM>>>(
        (const __nv_bfloat16*)p_h1, (const __nv_bfloat16*)p_Wout, b_out,
        out, MROWS, VV, HH, (float*)p_ps, 1);
    rowlog_k<<<MROWS/8, 256>>>((const float*)p_ps);
    logsm_apply_k<<<dim3((VV/4 + 255)/256, MROWS), 256>>>(out);
}